// round 6
// baseline (speedup 1.0000x reference)
#include <cuda_runtime.h>
#include <cuda_bf16.h>
#include <cstdint>

// Problem constants
#define NB 4
#define NS 2048
#define ND 2048
#define NH 16
#define HD 128
#define ATT_SCALE 0.08838834764831845f

// ---------------------------------------------------------------------------
// Scratch (device globals; allocation inside kernel_launch is forbidden)
// ---------------------------------------------------------------------------
#define TOK (NB * NS)                 // 8192 tokens
__device__ __align__(16) __nv_bfloat16 g_xh[TOK * ND];
__device__ __align__(16) __nv_bfloat16 g_xl[TOK * ND];
__device__ __align__(16) __nv_bfloat16 g_wth[4][ND * ND];   // W^T hi (q,k,v,o)
__device__ __align__(16) __nv_bfloat16 g_wtl[4][ND * ND];
__device__ __align__(16) __nv_bfloat16 g_qh[TOK * ND];
__device__ __align__(16) __nv_bfloat16 g_ql[TOK * ND];
__device__ __align__(16) __nv_bfloat16 g_kh[TOK * ND];
__device__ __align__(16) __nv_bfloat16 g_kl[TOK * ND];
__device__ __align__(16) float         g_v [TOK * ND];
__device__ __align__(16) __nv_bfloat16 g_vth[TOK * ND];     // V^T per batch [D][S]
__device__ __align__(16) __nv_bfloat16 g_vtl[TOK * ND];
__device__ __align__(16) __nv_bfloat16 g_oh[TOK * ND];
__device__ __align__(16) __nv_bfloat16 g_ol[TOK * ND];

// ---------------------------------------------------------------------------
// helpers
// ---------------------------------------------------------------------------
__device__ __forceinline__ uint32_t smem_u32(const void* p) {
    uint32_t a;
    asm("{ .reg .u64 t; cvta.to.shared.u64 t, %1; cvt.u32.u64 %0, t; }"
        : "=r"(a) : "l"(p));
    return a;
}
__device__ __forceinline__ void cpa16(uint32_t dst, const void* src) {
    asm volatile("cp.async.cg.shared.global [%0], [%1], 16;"
                 :: "r"(dst), "l"(src) : "memory");
}
#define CP_COMMIT() asm volatile("cp.async.commit_group;" ::: "memory")
#define CP_WAIT0()  asm volatile("cp.async.wait_group 0;" ::: "memory")
#define CP_WAIT1()  asm volatile("cp.async.wait_group 1;" ::: "memory")

__device__ __forceinline__ void ldsm4(uint32_t* r, uint32_t addr) {
    asm volatile("ldmatrix.sync.aligned.m8n8.x4.shared.b16 {%0,%1,%2,%3}, [%4];"
                 : "=r"(r[0]), "=r"(r[1]), "=r"(r[2]), "=r"(r[3]) : "r"(addr));
}
__device__ __forceinline__ void mma16816(float* d, const uint32_t* a,
                                         const uint32_t* b) {
    asm volatile(
        "mma.sync.aligned.m16n8k16.row.col.f32.bf16.bf16.f32 "
        "{%0,%1,%2,%3}, {%4,%5,%6,%7}, {%8,%9}, {%0,%1,%2,%3};"
        : "+f"(d[0]), "+f"(d[1]), "+f"(d[2]), "+f"(d[3])
        : "r"(a[0]), "r"(a[1]), "r"(a[2]), "r"(a[3]), "r"(b[0]), "r"(b[1]));
}
__device__ __forceinline__ void split2(float v, __nv_bfloat16& h, __nv_bfloat16& l) {
    h = __float2bfloat16(v);
    l = __float2bfloat16(v - __bfloat162float(h));
}
// pack (e0,e1) -> bf16x2 hi pair + lo (residual) pair; low half = e0
__device__ __forceinline__ void split_pair(float e0, float e1,
                                           uint32_t& hp, uint32_t& lp) {
    asm("cvt.rn.satfinite.bf16x2.f32 %0, %1, %2;" : "=r"(hp) : "f"(e1), "f"(e0));
    __nv_bfloat162 hb = *reinterpret_cast<__nv_bfloat162*>(&hp);
    const float l0 = e0 - __bfloat162float(hb.x);
    const float l1 = e1 - __bfloat162float(hb.y);
    asm("cvt.rn.satfinite.bf16x2.f32 %0, %1, %2;" : "=r"(lp) : "f"(l1), "f"(l0));
}

// ---------------------------------------------------------------------------
// GEMM: C[M,N] = alpha * A[M,K] * B[N,K]^T (+bias), split-bf16 3-product,
// warp-level mma.sync. Tiles 128x128, K-chunk 64, cp.async double buffer.
// OMODE 0: fp32 out; 1: split bf16 hi/lo out.
// ---------------------------------------------------------------------------
#define SMEM_BYTES (2 * 65536)

template <int OMODE>
__global__ void __launch_bounds__(256, 1) gemm_wm(
    const __nv_bfloat16* __restrict__ Ah, const __nv_bfloat16* __restrict__ Al,
    const __nv_bfloat16* __restrict__ Bh, const __nv_bfloat16* __restrict__ Bl,
    const float* __restrict__ bias, float alpha,
    float* __restrict__ Cf, __nv_bfloat16* __restrict__ Ch,
    __nv_bfloat16* __restrict__ Cl,
    int K, int lda, int ldb, int ldc)
{
    extern __shared__ char smem[];
    const int tid = threadIdx.x;
    const uint32_t sb32 = smem_u32(smem);

    const int m0 = blockIdx.y * 128;
    const int n0 = blockIdx.x * 128;

    const int rb = tid >> 3;
    const int cc8 = (tid & 7) * 8;
    long long aoff[4], boff[4];
    uint32_t swo[4];
    #pragma unroll
    for (int j = 0; j < 4; ++j) {
        const int row = j * 32 + rb;
        aoff[j] = (long long)(m0 + row) * lda + cc8;
        boff[j] = (long long)(n0 + row) * ldb + cc8;
        const uint32_t bo = row * 128 + (tid & 7) * 16;
        swo[j] = bo ^ ((bo >> 3) & 0x70);
    }

    const int lane = tid & 31, warp = tid >> 5;
    const int wm = warp >> 2;
    const int wn = warp & 3;
    const int sx = lane & 7;
    const int am8 = (lane >> 3) & 1;
    const int ach = (lane >> 4) & 1;
    const int bn8 = (lane >> 4) & 1;
    const int bch = (lane >> 3) & 1;
    uint32_t aro[4], bro[2];
    #pragma unroll
    for (int i = 0; i < 4; ++i)
        aro[i] = (uint32_t)(wm * 64 + i * 16 + sx + am8 * 8) * 128;
    #pragma unroll
    for (int j2 = 0; j2 < 2; ++j2)
        bro[j2] = (uint32_t)(wn * 32 + j2 * 16 + sx + bn8 * 8) * 128;

    float acc[4][4][4];
    #pragma unroll
    for (int i = 0; i < 4; ++i)
        #pragma unroll
        for (int j = 0; j < 4; ++j)
            #pragma unroll
            for (int e = 0; e < 4; ++e) acc[i][j][e] = 0.0f;

    {
        const uint32_t db = sb32;
        #pragma unroll
        for (int j = 0; j < 4; ++j) {
            cpa16(db + 0     + swo[j], Ah + aoff[j]);
            cpa16(db + 16384 + swo[j], Al + aoff[j]);
            cpa16(db + 32768 + swo[j], Bh + boff[j]);
            cpa16(db + 49152 + swo[j], Bl + boff[j]);
        }
        CP_COMMIT();
        CP_WAIT0();
    }
    __syncthreads();

    const int nT = K >> 6;
    for (int t = 0; t < nT; ++t) {
        if (t + 1 < nT) {
            const int k0 = (t + 1) << 6;
            const uint32_t db = sb32 + ((t + 1) & 1) * 65536;
            #pragma unroll
            for (int j = 0; j < 4; ++j) {
                cpa16(db + 0     + swo[j], Ah + aoff[j] + k0);
                cpa16(db + 16384 + swo[j], Al + aoff[j] + k0);
                cpa16(db + 32768 + swo[j], Bh + boff[j] + k0);
                cpa16(db + 49152 + swo[j], Bl + boff[j] + k0);
            }
            CP_COMMIT();
        }

        const uint32_t Abase = sb32 + (t & 1) * 65536;
        const uint32_t Bbase = Abase + 32768;
        #pragma unroll
        for (int ks = 0; ks < 4; ++ks) {
            uint32_t ah[4][4], alr[4][4], bh[4][2], bl[4][2];
            #pragma unroll
            for (int i = 0; i < 4; ++i) {
                const uint32_t off = aro[i] +
                    ((uint32_t)(((ks << 1) | ach) ^ sx) << 4);
                ldsm4(ah[i],  Abase + off);
                ldsm4(alr[i], Abase + 16384 + off);
            }
            #pragma unroll
            for (int j2 = 0; j2 < 2; ++j2) {
                const uint32_t off = bro[j2] +
                    ((uint32_t)(((ks << 1) | bch) ^ sx) << 4);
                uint32_t r[4], r2[4];
                ldsm4(r,  Bbase + off);
                ldsm4(r2, Bbase + 16384 + off);
                bh[j2 * 2][0] = r[0];  bh[j2 * 2][1] = r[1];
                bh[j2 * 2 + 1][0] = r[2];  bh[j2 * 2 + 1][1] = r[3];
                bl[j2 * 2][0] = r2[0]; bl[j2 * 2][1] = r2[1];
                bl[j2 * 2 + 1][0] = r2[2]; bl[j2 * 2 + 1][1] = r2[3];
            }
            #pragma unroll
            for (int i = 0; i < 4; ++i)
                #pragma unroll
                for (int j = 0; j < 4; ++j) {
                    mma16816(acc[i][j], ah[i],  bh[j]);
                    mma16816(acc[i][j], alr[i], bh[j]);
                    mma16816(acc[i][j], ah[i],  bl[j]);
                }
        }

        if (t + 1 < nT) CP_WAIT0();
        __syncthreads();
    }

    const int erow = m0 + wm * 64 + (lane >> 2);
    const int ecol = n0 + wn * 32 + (lane & 3) * 2;
    #pragma unroll
    for (int j = 0; j < 4; ++j) {
        const int c = ecol + j * 8;
        const float b0 = bias ? __ldg(bias + c)     : 0.0f;
        const float b1 = bias ? __ldg(bias + c + 1) : 0.0f;
        #pragma unroll
        for (int i = 0; i < 4; ++i) {
            const long long r0 = erow + i * 16;
            const float v0 = acc[i][j][0] * alpha + b0;
            const float v1 = acc[i][j][1] * alpha + b1;
            const float v2 = acc[i][j][2] * alpha + b0;
            const float v3 = acc[i][j][3] * alpha + b1;
            const long long o0 = r0 * (long long)ldc + c;
            const long long o1 = o0 + 8ll * ldc;
            if (OMODE == 0) {
                *(float2*)(Cf + o0) = make_float2(v0, v1);
                *(float2*)(Cf + o1) = make_float2(v2, v3);
            } else {
                uint32_t hp, lp;
                split_pair(v0, v1, hp, lp);
                *(uint32_t*)(Ch + o0) = hp;
                *(uint32_t*)(Cl + o0) = lp;
                split_pair(v2, v3, hp, lp);
                *(uint32_t*)(Ch + o1) = hp;
                *(uint32_t*)(Cl + o1) = lp;
            }
        }
    }
}

// ---------------------------------------------------------------------------
// Flash attention: per (b,h), per 128-row q-tile: O = softmax(Q K^T * sc) V.
// Q tile pinned in smem (hi/lo), K/V tiles (64 tokens) double-buffered.
// S never touches global memory; P converted C-frag -> A-frag in registers.
// smem: Q 64KB @0 (Qh0,Qh1,Ql0,Ql1 16KB blocks) ; stage s @65536+s*65536:
//   Kh0 8KB, Kh1, Kl0, Kl1, Vh 16KB @+32768, Vl @+49152
// ---------------------------------------------------------------------------
#define FL_SMEM 196608

__device__ __forceinline__ void fl_load_kv(
    uint32_t kb, int tid, int k0,
    const __nv_bfloat16* __restrict__ Kh, const __nv_bfloat16* __restrict__ Kl,
    const __nv_bfloat16* __restrict__ Vh, const __nv_bfloat16* __restrict__ Vl)
{
    #pragma unroll
    for (int q = 0; q < 2; ++q) {
        const int idx = tid + q * 256;
        const int row = idx >> 3, c8 = idx & 7;
        const uint32_t bo = row * 128 + c8 * 16;
        const uint32_t sw = bo ^ ((bo >> 3) & 0x70);
        #pragma unroll
        for (int blk = 0; blk < 2; ++blk) {
            const long long off = (long long)(k0 + row) * ND + blk * 64 + c8 * 8;
            cpa16(kb + blk * 8192 + sw, Kh + off);
            cpa16(kb + 16384 + blk * 8192 + sw, Kl + off);
        }
    }
    #pragma unroll
    for (int q = 0; q < 4; ++q) {
        const int idx = tid + q * 256;
        const int row = idx >> 3, c8 = idx & 7;
        const uint32_t bo = row * 128 + c8 * 16;
        const uint32_t sw = bo ^ ((bo >> 3) & 0x70);
        const long long off = (long long)row * NS + k0 + c8 * 8;
        cpa16(kb + 32768 + sw, Vh + off);
        cpa16(kb + 49152 + sw, Vl + off);
    }
    CP_COMMIT();
}

__global__ void __launch_bounds__(256, 1) flash_k(
    const __nv_bfloat16* __restrict__ Qh, const __nv_bfloat16* __restrict__ Ql,
    const __nv_bfloat16* __restrict__ Kh, const __nv_bfloat16* __restrict__ Kl,
    const __nv_bfloat16* __restrict__ Vh, const __nv_bfloat16* __restrict__ Vl,
    __nv_bfloat16* __restrict__ Oh, __nv_bfloat16* __restrict__ Ol)
{
    extern __shared__ char smem[];
    const int tid = threadIdx.x;
    const uint32_t sb = smem_u32(smem);

    const int bz = blockIdx.z;
    const int zb = bz >> 4, zh = bz & 15;
    const long long qkb = (long long)zb * NS * ND + zh * HD;
    Qh += qkb; Ql += qkb; Kh += qkb; Kl += qkb;
    const long long vb = (long long)zb * NS * ND + (long long)zh * HD * NS;
    Vh += vb; Vl += vb;

    const int m0 = blockIdx.y * 128;

    // ---- load Q tile ----
    #pragma unroll
    for (int blk = 0; blk < 2; ++blk)
        #pragma unroll
        for (int q = 0; q < 4; ++q) {
            const int idx = tid + q * 256;
            const int row = idx >> 3, c8 = idx & 7;
            const uint32_t bo = row * 128 + c8 * 16;
            const uint32_t sw = bo ^ ((bo >> 3) & 0x70);
            const long long off = (long long)(m0 + row) * ND + blk * 64 + c8 * 8;
            cpa16(sb + blk * 16384 + sw, Qh + off);
            cpa16(sb + 32768 + blk * 16384 + sw, Ql + off);
        }
    CP_COMMIT();
    fl_load_kv(sb + 65536, tid, 0, Kh, Kl, Vh, Vl);

    // ---- warp geometry ----
    const int lane = tid & 31, warp = tid >> 5;
    const int sx = lane & 7;
    const int am8 = (lane >> 3) & 1, ach = (lane >> 4) & 1;
    const int bn8 = (lane >> 4) & 1, bch = (lane >> 3) & 1;
    const uint32_t aroQ = (uint32_t)(warp * 16 + sx + am8 * 8) * 128;
    uint32_t bgK[4], bgV[8];
    #pragma unroll
    for (int g = 0; g < 4; ++g)
        bgK[g] = (uint32_t)(g * 16 + sx + bn8 * 8) * 128;
    #pragma unroll
    for (int g = 0; g < 8; ++g)
        bgV[g] = (uint32_t)(g * 16 + sx + bn8 * 8) * 128;

    float accO[16][4];
    #pragma unroll
    for (int j = 0; j < 16; ++j)
        #pragma unroll
        for (int e = 0; e < 4; ++e) accO[j][e] = 0.0f;
    float ls0 = 0.0f, ls1 = 0.0f;

    for (int t = 0; t < 32; ++t) {
        if (t + 1 < 32)
            fl_load_kv(sb + 65536 + ((t + 1) & 1) * 65536, tid, (t + 1) << 6,
                       Kh, Kl, Vh, Vl);
        if (t + 1 < 32) CP_WAIT1(); else CP_WAIT0();
        __syncthreads();

        const uint32_t kbb = sb + 65536 + (t & 1) * 65536;

        // ---- QK: S[16 x 64] per warp ----
        float accS[8][4];
        #pragma unroll
        for (int j = 0; j < 8; ++j)
            #pragma unroll
            for (int e = 0; e < 4; ++e) accS[j][e] = 0.0f;

        #pragma unroll
        for (int ks = 0; ks < 8; ++ks) {
            const uint32_t kk = (uint32_t)((((ks & 3) << 1) | ach) ^ sx) << 4;
            const uint32_t kkb = (uint32_t)((((ks & 3) << 1) | bch) ^ sx) << 4;
            uint32_t ah[4], al[4];
            const uint32_t aaddr = sb + (ks >> 2) * 16384 + aroQ + kk;
            ldsm4(ah, aaddr);
            ldsm4(al, aaddr + 32768);
            #pragma unroll
            for (int g = 0; g < 4; ++g) {
                const uint32_t baddr = kbb + (ks >> 2) * 8192 + bgK[g] + kkb;
                uint32_t r[4], r2[4];
                ldsm4(r, baddr);
                ldsm4(r2, baddr + 16384);
                uint32_t b0[2] = {r[0], r[1]},  b1[2] = {r[2], r[3]};
                uint32_t c0[2] = {r2[0], r2[1]}, c1[2] = {r2[2], r2[3]};
                mma16816(accS[2 * g],     ah, b0);
                mma16816(accS[2 * g],     al, b0);
                mma16816(accS[2 * g],     ah, c0);
                mma16816(accS[2 * g + 1], ah, b1);
                mma16816(accS[2 * g + 1], al, b1);
                mma16816(accS[2 * g + 1], ah, c1);
            }
        }

        // ---- exp + row-sum + pack P fragments (C-frag == A-frag layout) ----
        uint32_t phf[4][4], plf[4][4];
        #pragma unroll
        for (int j = 0; j < 8; ++j) {
            const float e0 = __expf(accS[j][0] * ATT_SCALE);
            const float e1 = __expf(accS[j][1] * ATT_SCALE);
            const float e2 = __expf(accS[j][2] * ATT_SCALE);
            const float e3 = __expf(accS[j][3] * ATT_SCALE);
            ls0 += e0 + e1;
            ls1 += e2 + e3;
            const int kt = j >> 1, hh = (j & 1) * 2;
            split_pair(e0, e1, phf[kt][hh],     plf[kt][hh]);
            split_pair(e2, e3, phf[kt][hh + 1], plf[kt][hh + 1]);
        }

        // ---- PV: O[16 x 128] += P[16 x 64] * V^T ----
        #pragma unroll
        for (int ks = 0; ks < 4; ++ks) {
            const uint32_t kkb = (uint32_t)(((ks << 1) | bch) ^ sx) << 4;
            #pragma unroll
            for (int g = 0; g < 8; ++g) {
                const uint32_t vaddr = kbb + 32768 + bgV[g] + kkb;
                uint32_t r[4], r2[4];
                ldsm4(r, vaddr);
                ldsm4(r2, vaddr + 16384);
                uint32_t b0[2] = {r[0], r[1]},  b1[2] = {r[2], r[3]};
                uint32_t c0[2] = {r2[0], r2[1]}, c1[2] = {r2[2], r2[3]};
                mma16816(accO[2 * g],     phf[ks], b0);
                mma16816(accO[2 * g],     plf[ks], b0);
                mma16816(accO[2 * g],     phf[ks], c0);
                mma16816(accO[2 * g + 1], phf[ks], b1);
                mma16816(accO[2 * g + 1], plf[ks], b1);
                mma16816(accO[2 * g + 1], phf[ks], c1);
            }
        }
        __syncthreads();
    }

    // ---- epilogue: reduce row sums across quad, divide, split, store ----
    ls0 += __shfl_xor_sync(0xffffffffu, ls0, 1);
    ls0 += __shfl_xor_sync(0xffffffffu, ls0, 2);
    ls1 += __shfl_xor_sync(0xffffffffu, ls1, 1);
    ls1 += __shfl_xor_sync(0xffffffffu, ls1, 2);
    const float inv0 = 1.0f / ls0;
    const float inv1 = 1.0f / ls1;

    const long long obase = qkb;   // same layout as Q: token*ND + zh*HD
    const int row0 = m0 + warp * 16 + (lane >> 2);
    #pragma unroll
    for (int j = 0; j < 16; ++j) {
        const int c = j * 8 + (lane & 3) * 2;
        const long long o0 = obase + (long long)row0 * ND + c;
        const long long o1 = o0 + 8ll * ND;
        uint32_t hp, lp;
        split_pair(accO[j][0] * inv0, accO[j][1] * inv0, hp, lp);
        *(uint32_t*)(Oh + o0) = hp;
        *(uint32_t*)(Ol + o0) = lp;
        split_pair(accO[j][2] * inv1, accO[j][3] * inv1, hp, lp);
        *(uint32_t*)(Oh + o1) = hp;
        *(uint32_t*)(Ol + o1) = lp;
    }
}

// ---------------------------------------------------------------------------
// fp32 -> split bf16 (elementwise)
// ---------------------------------------------------------------------------
__global__ void __launch_bounds__(256) split_k(const float* __restrict__ in,
                                               __nv_bfloat16* __restrict__ oh,
                                               __nv_bfloat16* __restrict__ ol,
                                               long long n)
{
    for (long long i = blockIdx.x * 256ll + threadIdx.x; i < n;
         i += (long long)gridDim.x * 256) {
        __nv_bfloat16 h, l;
        split2(in[i], h, l);
        oh[i] = h; ol[i] = l;
    }
}

// ---------------------------------------------------------------------------
// transpose + split: in fp32 [R][C] row-major -> out hi/lo [C][R]
// ---------------------------------------------------------------------------
__global__ void __launch_bounds__(256) tsplit_k(const float* __restrict__ in,
                                                __nv_bfloat16* __restrict__ oh,
                                                __nv_bfloat16* __restrict__ ol,
                                                int R, int C,
                                                long long inB, long long outB)
{
    __shared__ float t[32][33];
    const int b = blockIdx.z;
    in += b * inB; oh += b * outB; ol += b * outB;
    const int x = blockIdx.x * 32 + threadIdx.x;
    const int y0 = blockIdx.y * 32;
    #pragma unroll
    for (int i = 0; i < 4; ++i)
        t[threadIdx.y + i * 8][threadIdx.x] =
            in[(long long)(y0 + threadIdx.y + i * 8) * C + x];
    __syncthreads();
    const int ox = y0 + threadIdx.x;
    const int oy = blockIdx.x * 32;
    #pragma unroll
    for (int i = 0; i < 4; ++i) {
        const float v = t[threadIdx.x][threadIdx.y + i * 8];
        __nv_bfloat16 h, l;
        split2(v, h, l);
        const long long o = (long long)(oy + threadIdx.y + i * 8) * R + ox;
        oh[o] = h; ol[o] = l;
    }
}

// ---------------------------------------------------------------------------
extern "C" void kernel_launch(void* const* d_in, const int* in_sizes, int n_in,
                              void* d_out, int out_size)
{
    (void)in_sizes; (void)n_in; (void)out_size;
    const float* x  = (const float*)d_in[0];
    const float* W[4] = { (const float*)d_in[2], (const float*)d_in[4],
                          (const float*)d_in[6], (const float*)d_in[8] };
    const float* bq = (const float*)d_in[3];
    const float* bk = (const float*)d_in[5];
    const float* bv = (const float*)d_in[7];
    const float* bo = (const float*)d_in[9];
    float* out = (float*)d_out;

    __nv_bfloat16 *xh, *xl, *wth, *wtl, *qh, *ql, *kh, *kl, *vth, *vtl;
    __nv_bfloat16 *oh, *ol;
    float *v32;
    cudaGetSymbolAddress((void**)&xh,  g_xh);
    cudaGetSymbolAddress((void**)&xl,  g_xl);
    cudaGetSymbolAddress((void**)&wth, g_wth);
    cudaGetSymbolAddress((void**)&wtl, g_wtl);
    cudaGetSymbolAddress((void**)&qh,  g_qh);
    cudaGetSymbolAddress((void**)&ql,  g_ql);
    cudaGetSymbolAddress((void**)&kh,  g_kh);
    cudaGetSymbolAddress((void**)&kl,  g_kl);
    cudaGetSymbolAddress((void**)&v32, g_v);
    cudaGetSymbolAddress((void**)&vth, g_vth);
    cudaGetSymbolAddress((void**)&vtl, g_vtl);
    cudaGetSymbolAddress((void**)&oh,  g_oh);
    cudaGetSymbolAddress((void**)&ol,  g_ol);

    cudaFuncSetAttribute(gemm_wm<0>, cudaFuncAttributeMaxDynamicSharedMemorySize,
                         SMEM_BYTES);
    cudaFuncSetAttribute(gemm_wm<1>, cudaFuncAttributeMaxDynamicSharedMemorySize,
                         SMEM_BYTES);
    cudaFuncSetAttribute(flash_k, cudaFuncAttributeMaxDynamicSharedMemorySize,
                         FL_SMEM);

    const dim3 blk(256, 1, 1);
    const long long sSD = (long long)NS * ND;
    const long long WSZ = (long long)ND * ND;

    // 1) split x; transpose+split weights
    split_k<<<32768, blk>>>(x, xh, xl, (long long)TOK * ND);
    {
        dim3 g(ND / 32, ND / 32, 1), b(32, 8, 1);
        for (int i = 0; i < 4; ++i)
            tsplit_k<<<g, b>>>(W[i], wth + i * WSZ, wtl + i * WSZ, ND, ND, 0, 0);
    }

    // 2) projections
    const dim3 gproj(ND / 128, TOK / 128, 1);
    gemm_wm<1><<<gproj, blk, SMEM_BYTES>>>(xh, xl, wth + 0 * WSZ, wtl + 0 * WSZ,
        bq, 1.0f, nullptr, qh, ql, ND, ND, ND, ND);
    gemm_wm<1><<<gproj, blk, SMEM_BYTES>>>(xh, xl, wth + 1 * WSZ, wtl + 1 * WSZ,
        bk, 1.0f, nullptr, kh, kl, ND, ND, ND, ND);
    gemm_wm<0><<<gproj, blk, SMEM_BYTES>>>(xh, xl, wth + 2 * WSZ, wtl + 2 * WSZ,
        bv, 1.0f, v32, nullptr, nullptr, ND, ND, ND, ND);

    // 3) transpose+split V per batch: [S,D] -> [D,S]
    {
        dim3 g(ND / 32, NS / 32, NB), b(32, 8, 1);
        tsplit_k<<<g, b>>>(v32, vth, vtl, NS, ND, sSD, sSD);
    }

    // 4) flash attention (QK + softmax + PV fused; S never in DRAM)
    {
        dim3 g(1, NS / 128, NB * NH);
        flash_k<<<g, blk, FL_SMEM>>>(qh, ql, kh, kl, vth, vtl, oh, ol);
    }

    // 5) final projection -> d_out
    gemm_wm<0><<<gproj, blk, SMEM_BYTES>>>(oh, ol, wth + 3 * WSZ, wtl + 3 * WSZ,
        bo, 1.0f, out, nullptr, nullptr, ND, ND, ND, ND);
}

// round 7
// speedup vs baseline: 1.2616x; 1.2616x over previous
#include <cuda_runtime.h>
#include <cuda_bf16.h>
#include <cstdint>

// Problem constants
#define NB 4
#define NS 2048
#define ND 2048
#define NH 16
#define HD 128
#define ATT_SCALE 0.08838834764831845f

// ---------------------------------------------------------------------------
// Scratch (device globals; allocation inside kernel_launch is forbidden)
// ---------------------------------------------------------------------------
#define TOK (NB * NS)                 // 8192 tokens
__device__ __align__(16) __nv_bfloat16 g_xh[TOK * ND];
__device__ __align__(16) __nv_bfloat16 g_xl[TOK * ND];
__device__ __align__(16) __nv_bfloat16 g_wth[4][ND * ND];   // W^T hi (q,k,v,o)
__device__ __align__(16) __nv_bfloat16 g_wtl[4][ND * ND];
__device__ __align__(16) __nv_bfloat16 g_qh[TOK * ND];
__device__ __align__(16) __nv_bfloat16 g_ql[TOK * ND];
__device__ __align__(16) __nv_bfloat16 g_kh[TOK * ND];
__device__ __align__(16) __nv_bfloat16 g_kl[TOK * ND];
__device__ __align__(16) float         g_v [TOK * ND];
__device__ __align__(16) __nv_bfloat16 g_vth[TOK * ND];     // V^T per batch [D][S]
__device__ __align__(16) __nv_bfloat16 g_vtl[TOK * ND];
__device__ __align__(16) float         g_s [(long long)NB * NH * NS * NS]; // 1 GB
__device__ __align__(16) __nv_bfloat16 g_oh[TOK * ND];
__device__ __align__(16) __nv_bfloat16 g_ol[TOK * ND];

// ---------------------------------------------------------------------------
// helpers
// ---------------------------------------------------------------------------
__device__ __forceinline__ uint32_t smem_u32(const void* p) {
    uint32_t a;
    asm("{ .reg .u64 t; cvta.to.shared.u64 t, %1; cvt.u32.u64 %0, t; }"
        : "=r"(a) : "l"(p));
    return a;
}
__device__ __forceinline__ void cpa16(uint32_t dst, const void* src) {
    asm volatile("cp.async.cg.shared.global [%0], [%1], 16;"
                 :: "r"(dst), "l"(src) : "memory");
}
#define CP_COMMIT() asm volatile("cp.async.commit_group;" ::: "memory")
#define CP_WAIT0()  asm volatile("cp.async.wait_group 0;" ::: "memory")
#define CP_WAIT1()  asm volatile("cp.async.wait_group 1;" ::: "memory")

__device__ __forceinline__ void ldsm4(uint32_t* r, uint32_t addr) {
    asm volatile("ldmatrix.sync.aligned.m8n8.x4.shared.b16 {%0,%1,%2,%3}, [%4];"
                 : "=r"(r[0]), "=r"(r[1]), "=r"(r[2]), "=r"(r[3]) : "r"(addr));
}
__device__ __forceinline__ void mma16816(float* d, const uint32_t* a,
                                         const uint32_t* b) {
    asm volatile(
        "mma.sync.aligned.m16n8k16.row.col.f32.bf16.bf16.f32 "
        "{%0,%1,%2,%3}, {%4,%5,%6,%7}, {%8,%9}, {%0,%1,%2,%3};"
        : "+f"(d[0]), "+f"(d[1]), "+f"(d[2]), "+f"(d[3])
        : "r"(a[0]), "r"(a[1]), "r"(a[2]), "r"(a[3]), "r"(b[0]), "r"(b[1]));
}
__device__ __forceinline__ void split2(float v, __nv_bfloat16& h, __nv_bfloat16& l) {
    h = __float2bfloat16(v);
    l = __float2bfloat16(v - __bfloat162float(h));
}
// pack (e0,e1) -> bf16x2 hi pair + lo (residual) pair; low half = e0
__device__ __forceinline__ void split_pair(float e0, float e1,
                                           uint32_t& hp, uint32_t& lp) {
    asm("cvt.rn.satfinite.bf16x2.f32 %0, %1, %2;" : "=r"(hp) : "f"(e1), "f"(e0));
    __nv_bfloat162 hb = *reinterpret_cast<__nv_bfloat162*>(&hp);
    const float l0 = e0 - __bfloat162float(hb.x);
    const float l1 = e1 - __bfloat162float(hb.y);
    asm("cvt.rn.satfinite.bf16x2.f32 %0, %1, %2;" : "=r"(lp) : "f"(l1), "f"(l0));
}

// ---------------------------------------------------------------------------
// gemm_big: 512 threads, tile 256x128, K-chunk 64, 2 stages (192 KB smem).
// C[M,N] = alpha * A[M,K] * B[N,K]^T (+bias). Non-batched (projections).
// OMODE 0: fp32 out; 1: split bf16 hi/lo out.
// smem stage layout: Ah 32K @0, Al @32768, Bh 16K @65536, Bl @81920; stage size 98304.
// ---------------------------------------------------------------------------
#define BIG_SMEM (2 * 98304)

template <int OMODE>
__global__ void __launch_bounds__(512, 1) gemm_big(
    const __nv_bfloat16* __restrict__ Ah, const __nv_bfloat16* __restrict__ Al,
    const __nv_bfloat16* __restrict__ Bh, const __nv_bfloat16* __restrict__ Bl,
    const float* __restrict__ bias, float alpha,
    float* __restrict__ Cf, __nv_bfloat16* __restrict__ Ch,
    __nv_bfloat16* __restrict__ Cl, int K)
{
    extern __shared__ char smem[];
    const int tid = threadIdx.x;
    const uint32_t sb32 = smem_u32(smem);

    const int m0 = blockIdx.y * 256;
    const int n0 = blockIdx.x * 128;

    // loader geometry: 16B chunks, row = j*64 + (tid>>3), col = (tid&7)*8
    const int rb = tid >> 3;                  // 0..63
    const int cc8 = (tid & 7) * 8;
    uint32_t aoff[4], boff[2], swa[4], swb[2];
    #pragma unroll
    for (int j = 0; j < 4; ++j) {
        const int row = j * 64 + rb;
        aoff[j] = (uint32_t)(m0 + row) * (uint32_t)K + cc8;
        const uint32_t bo = row * 128 + (tid & 7) * 16;
        swa[j] = bo ^ ((bo >> 3) & 0x70);
    }
    #pragma unroll
    for (int j = 0; j < 2; ++j) {
        const int row = j * 64 + rb;
        boff[j] = (uint32_t)(n0 + row) * (uint32_t)K + cc8;
        const uint32_t bo = row * 128 + (tid & 7) * 16;
        swb[j] = bo ^ ((bo >> 3) & 0x70);
    }

    // warp geometry: 16 warps = 4(m) x 4(n); warp tile 64x32
    const int lane = tid & 31, warp = tid >> 5;
    const int wm = warp >> 2;                 // 0..3
    const int wn = warp & 3;                  // 0..3
    const int sx = lane & 7;
    const int am8 = (lane >> 3) & 1;
    const int ach = (lane >> 4) & 1;
    const int bn8 = (lane >> 4) & 1;
    const int bch = (lane >> 3) & 1;
    uint32_t aro[4], bro[2];
    #pragma unroll
    for (int i = 0; i < 4; ++i)
        aro[i] = (uint32_t)(wm * 64 + i * 16 + sx + am8 * 8) * 128;
    #pragma unroll
    for (int j2 = 0; j2 < 2; ++j2)
        bro[j2] = (uint32_t)(wn * 32 + j2 * 16 + sx + bn8 * 8) * 128;

    float acc[4][4][4];
    #pragma unroll
    for (int i = 0; i < 4; ++i)
        #pragma unroll
        for (int j = 0; j < 4; ++j)
            #pragma unroll
            for (int e = 0; e < 4; ++e) acc[i][j][e] = 0.0f;

    // prologue: stage 0
    {
        const uint32_t db = sb32;
        #pragma unroll
        for (int j = 0; j < 4; ++j) {
            cpa16(db + swa[j],         Ah + aoff[j]);
            cpa16(db + 32768 + swa[j], Al + aoff[j]);
        }
        #pragma unroll
        for (int j = 0; j < 2; ++j) {
            cpa16(db + 65536 + swb[j], Bh + boff[j]);
            cpa16(db + 81920 + swb[j], Bl + boff[j]);
        }
        CP_COMMIT();
        CP_WAIT0();
    }
    __syncthreads();

    const int nT = K >> 6;
    for (int t = 0; t < nT; ++t) {
        if (t + 1 < nT) {
            const uint32_t k0 = (uint32_t)(t + 1) << 6;
            const uint32_t db = sb32 + ((t + 1) & 1) * 98304;
            #pragma unroll
            for (int j = 0; j < 4; ++j) {
                cpa16(db + swa[j],         Ah + aoff[j] + k0);
                cpa16(db + 32768 + swa[j], Al + aoff[j] + k0);
            }
            #pragma unroll
            for (int j = 0; j < 2; ++j) {
                cpa16(db + 65536 + swb[j], Bh + boff[j] + k0);
                cpa16(db + 81920 + swb[j], Bl + boff[j] + k0);
            }
            CP_COMMIT();
        }

        const uint32_t Abase = sb32 + (t & 1) * 98304;
        const uint32_t Bbase = Abase + 65536;
        #pragma unroll
        for (int ks = 0; ks < 4; ++ks) {
            uint32_t ah[4][4], alr[4][4], bh[4][2], bl[4][2];
            #pragma unroll
            for (int i = 0; i < 4; ++i) {
                const uint32_t off = aro[i] +
                    ((uint32_t)(((ks << 1) | ach) ^ sx) << 4);
                ldsm4(ah[i],  Abase + off);
                ldsm4(alr[i], Abase + 32768 + off);
            }
            #pragma unroll
            for (int j2 = 0; j2 < 2; ++j2) {
                const uint32_t off = bro[j2] +
                    ((uint32_t)(((ks << 1) | bch) ^ sx) << 4);
                uint32_t r[4], r2[4];
                ldsm4(r,  Bbase + off);
                ldsm4(r2, Bbase + 16384 + off);
                bh[j2 * 2][0] = r[0];  bh[j2 * 2][1] = r[1];
                bh[j2 * 2 + 1][0] = r[2];  bh[j2 * 2 + 1][1] = r[3];
                bl[j2 * 2][0] = r2[0]; bl[j2 * 2][1] = r2[1];
                bl[j2 * 2 + 1][0] = r2[2]; bl[j2 * 2 + 1][1] = r2[3];
            }
            #pragma unroll
            for (int i = 0; i < 4; ++i)
                #pragma unroll
                for (int j = 0; j < 4; ++j) {
                    mma16816(acc[i][j], ah[i],  bh[j]);
                    mma16816(acc[i][j], alr[i], bh[j]);
                    mma16816(acc[i][j], ah[i],  bl[j]);
                }
        }

        if (t + 1 < nT) CP_WAIT0();
        __syncthreads();
    }

    // epilogue
    const int erow = m0 + wm * 64 + (lane >> 2);
    const int ecol = n0 + wn * 32 + (lane & 3) * 2;
    #pragma unroll
    for (int j = 0; j < 4; ++j) {
        const int c = ecol + j * 8;
        const float b0 = bias ? __ldg(bias + c)     : 0.0f;
        const float b1 = bias ? __ldg(bias + c + 1) : 0.0f;
        #pragma unroll
        for (int i = 0; i < 4; ++i) {
            const uint32_t r0 = erow + i * 16;
            const float v0 = acc[i][j][0] * alpha + b0;
            const float v1 = acc[i][j][1] * alpha + b1;
            const float v2 = acc[i][j][2] * alpha + b0;
            const float v3 = acc[i][j][3] * alpha + b1;
            const uint32_t o0 = r0 * (uint32_t)ND + c;
            const uint32_t o1 = o0 + 8u * ND;
            if (OMODE == 0) {
                *(float2*)(Cf + o0) = make_float2(v0, v1);
                *(float2*)(Cf + o1) = make_float2(v2, v3);
            } else {
                uint32_t hp, lp;
                split_pair(v0, v1, hp, lp);
                *(uint32_t*)(Ch + o0) = hp;
                *(uint32_t*)(Cl + o0) = lp;
                split_pair(v2, v3, hp, lp);
                *(uint32_t*)(Ch + o1) = hp;
                *(uint32_t*)(Cl + o1) = lp;
            }
        }
    }
}

// ---------------------------------------------------------------------------
// gemm_wm: 256 threads, tile 128x128 (batched; used for QK scores).
// C = alpha * A[M,K] * B[N,K]^T -> fp32.
// ---------------------------------------------------------------------------
#define SMEM_BYTES (2 * 65536)

__global__ void __launch_bounds__(256, 1) gemm_wm(
    const __nv_bfloat16* __restrict__ Ah, const __nv_bfloat16* __restrict__ Al,
    const __nv_bfloat16* __restrict__ Bh, const __nv_bfloat16* __restrict__ Bl,
    float alpha, float* __restrict__ Cf,
    int K, int lda, int ldb, int ldc, int hdiv,
    long long sa1, long long sa2, long long sb1, long long sb2,
    long long sc1, long long sc2)
{
    extern __shared__ char smem[];
    const int tid = threadIdx.x;
    const uint32_t sb32 = smem_u32(smem);

    const int bz = blockIdx.z;
    const int zb = bz / hdiv;
    const int zh = bz - zb * hdiv;
    Ah += zb * sa1 + zh * sa2;  Al += zb * sa1 + zh * sa2;
    Bh += zb * sb1 + zh * sb2;  Bl += zb * sb1 + zh * sb2;
    const long long coff = zb * sc1 + zh * sc2;

    const int m0 = blockIdx.y * 128;
    const int n0 = blockIdx.x * 128;

    const int rb = tid >> 3;
    const int cc8 = (tid & 7) * 8;
    long long aoff[4], boff[4];
    uint32_t swo[4];
    #pragma unroll
    for (int j = 0; j < 4; ++j) {
        const int row = j * 32 + rb;
        aoff[j] = (long long)(m0 + row) * lda + cc8;
        boff[j] = (long long)(n0 + row) * ldb + cc8;
        const uint32_t bo = row * 128 + (tid & 7) * 16;
        swo[j] = bo ^ ((bo >> 3) & 0x70);
    }

    const int lane = tid & 31, warp = tid >> 5;
    const int wm = warp >> 2;
    const int wn = warp & 3;
    const int sx = lane & 7;
    const int am8 = (lane >> 3) & 1;
    const int ach = (lane >> 4) & 1;
    const int bn8 = (lane >> 4) & 1;
    const int bch = (lane >> 3) & 1;
    uint32_t aro[4], bro[2];
    #pragma unroll
    for (int i = 0; i < 4; ++i)
        aro[i] = (uint32_t)(wm * 64 + i * 16 + sx + am8 * 8) * 128;
    #pragma unroll
    for (int j2 = 0; j2 < 2; ++j2)
        bro[j2] = (uint32_t)(wn * 32 + j2 * 16 + sx + bn8 * 8) * 128;

    float acc[4][4][4];
    #pragma unroll
    for (int i = 0; i < 4; ++i)
        #pragma unroll
        for (int j = 0; j < 4; ++j)
            #pragma unroll
            for (int e = 0; e < 4; ++e) acc[i][j][e] = 0.0f;

    {
        const uint32_t db = sb32;
        #pragma unroll
        for (int j = 0; j < 4; ++j) {
            cpa16(db + 0     + swo[j], Ah + aoff[j]);
            cpa16(db + 16384 + swo[j], Al + aoff[j]);
            cpa16(db + 32768 + swo[j], Bh + boff[j]);
            cpa16(db + 49152 + swo[j], Bl + boff[j]);
        }
        CP_COMMIT();
        CP_WAIT0();
    }
    __syncthreads();

    const int nT = K >> 6;
    for (int t = 0; t < nT; ++t) {
        if (t + 1 < nT) {
            const int k0 = (t + 1) << 6;
            const uint32_t db = sb32 + ((t + 1) & 1) * 65536;
            #pragma unroll
            for (int j = 0; j < 4; ++j) {
                cpa16(db + 0     + swo[j], Ah + aoff[j] + k0);
                cpa16(db + 16384 + swo[j], Al + aoff[j] + k0);
                cpa16(db + 32768 + swo[j], Bh + boff[j] + k0);
                cpa16(db + 49152 + swo[j], Bl + boff[j] + k0);
            }
            CP_COMMIT();
        }

        const uint32_t Abase = sb32 + (t & 1) * 65536;
        const uint32_t Bbase = Abase + 32768;
        #pragma unroll
        for (int ks = 0; ks < 4; ++ks) {
            uint32_t ah[4][4], alr[4][4], bh[4][2], bl[4][2];
            #pragma unroll
            for (int i = 0; i < 4; ++i) {
                const uint32_t off = aro[i] +
                    ((uint32_t)(((ks << 1) | ach) ^ sx) << 4);
                ldsm4(ah[i],  Abase + off);
                ldsm4(alr[i], Abase + 16384 + off);
            }
            #pragma unroll
            for (int j2 = 0; j2 < 2; ++j2) {
                const uint32_t off = bro[j2] +
                    ((uint32_t)(((ks << 1) | bch) ^ sx) << 4);
                uint32_t r[4], r2[4];
                ldsm4(r,  Bbase + off);
                ldsm4(r2, Bbase + 16384 + off);
                bh[j2 * 2][0] = r[0];  bh[j2 * 2][1] = r[1];
                bh[j2 * 2 + 1][0] = r[2];  bh[j2 * 2 + 1][1] = r[3];
                bl[j2 * 2][0] = r2[0]; bl[j2 * 2][1] = r2[1];
                bl[j2 * 2 + 1][0] = r2[2]; bl[j2 * 2 + 1][1] = r2[3];
            }
            #pragma unroll
            for (int i = 0; i < 4; ++i)
                #pragma unroll
                for (int j = 0; j < 4; ++j) {
                    mma16816(acc[i][j], ah[i],  bh[j]);
                    mma16816(acc[i][j], alr[i], bh[j]);
                    mma16816(acc[i][j], ah[i],  bl[j]);
                }
        }

        if (t + 1 < nT) CP_WAIT0();
        __syncthreads();
    }

    const int erow = m0 + wm * 64 + (lane >> 2);
    const int ecol = n0 + wn * 32 + (lane & 3) * 2;
    #pragma unroll
    for (int j = 0; j < 4; ++j) {
        const int c = ecol + j * 8;
        #pragma unroll
        for (int i = 0; i < 4; ++i) {
            const long long r0 = erow + i * 16;
            const long long o0 = coff + r0 * ldc + c;
            const long long o1 = o0 + 8ll * ldc;
            *(float2*)(Cf + o0) = make_float2(acc[i][j][0] * alpha,
                                              acc[i][j][1] * alpha);
            *(float2*)(Cf + o1) = make_float2(acc[i][j][2] * alpha,
                                              acc[i][j][3] * alpha);
        }
    }
}

// ---------------------------------------------------------------------------
// Fused softmax + PV (proven in round 5)
// ---------------------------------------------------------------------------
#define PV_SMEM (131072 + 1024)

__global__ void __launch_bounds__(256, 1) pv_fused(
    const float* __restrict__ S,
    const __nv_bfloat16* __restrict__ Vh, const __nv_bfloat16* __restrict__ Vl,
    __nv_bfloat16* __restrict__ Ch, __nv_bfloat16* __restrict__ Cl)
{
    extern __shared__ char smem[];
    const int tid = threadIdx.x;
    const uint32_t sb = smem_u32(smem);
    float* lsm = (float*)(smem + 131072);

    const int bz = blockIdx.z;
    const int zb = bz >> 4, zh = bz & 15;
    S += (long long)bz * NS * NS;
    const long long vbase = (long long)zb * NS * ND + (long long)zh * HD * NS;
    Vh += vbase; Vl += vbase;
    const long long cbase = (long long)zb * NS * ND + zh * HD;

    const int m0 = blockIdx.y * 128;

    const int crow = tid >> 1, chalf = tid & 1;
    const float* sp = S + (long long)(m0 + crow) * NS + chalf * 32;
    uint32_t asw[4];
    #pragma unroll
    for (int q = 0; q < 4; ++q) {
        const uint32_t bo = crow * 128 + chalf * 64 + q * 16;
        asw[q] = bo ^ ((bo >> 3) & 0x70);
    }

    const int rb = tid >> 3, cc8 = (tid & 7) * 8;
    long long boff[4];
    uint32_t swo[4];
    #pragma unroll
    for (int j = 0; j < 4; ++j) {
        const int row = j * 32 + rb;
        boff[j] = (long long)row * NS + cc8;
        const uint32_t bo = row * 128 + (tid & 7) * 16;
        swo[j] = bo ^ ((bo >> 3) & 0x70);
    }

    const int lane = tid & 31, warp = tid >> 5;
    const int wm = warp >> 2, wn = warp & 3;
    const int sx = lane & 7;
    const int am8 = (lane >> 3) & 1, ach = (lane >> 4) & 1;
    const int bn8 = (lane >> 4) & 1, bch = (lane >> 3) & 1;
    uint32_t aro[4], bro[2];
    #pragma unroll
    for (int i = 0; i < 4; ++i)
        aro[i] = (uint32_t)(wm * 64 + i * 16 + sx + am8 * 8) * 128;
    #pragma unroll
    for (int j2 = 0; j2 < 2; ++j2)
        bro[j2] = (uint32_t)(wn * 32 + j2 * 16 + sx + bn8 * 8) * 128;

    float acc[4][4][4];
    #pragma unroll
    for (int i = 0; i < 4; ++i)
        #pragma unroll
        for (int j = 0; j < 4; ++j)
            #pragma unroll
            for (int e = 0; e < 4; ++e) acc[i][j][e] = 0.0f;

    float ls = 0.0f;
    uint4 pf[8];
    #pragma unroll
    for (int q = 0; q < 8; ++q) pf[q] = *(const uint4*)(sp + q * 4);
    {
        const uint32_t db = sb + 65536;
        #pragma unroll
        for (int j = 0; j < 4; ++j) {
            cpa16(db + swo[j],         Vh + boff[j]);
            cpa16(db + 16384 + swo[j], Vl + boff[j]);
        }
        CP_COMMIT();
    }

    for (int t = 0; t < 32; ++t) {
        const int st = t & 1;
        if (t + 1 < 32) {
            const uint32_t db = sb + 65536 + ((t + 1) & 1) * 32768;
            const int k0 = (t + 1) << 6;
            #pragma unroll
            for (int j = 0; j < 4; ++j) {
                cpa16(db + swo[j],         Vh + boff[j] + k0);
                cpa16(db + 16384 + swo[j], Vl + boff[j] + k0);
            }
            CP_COMMIT();
        }

        {
            char* ab = smem + st * 32768;
            #pragma unroll
            for (int qq = 0; qq < 4; ++qq) {
                const float4 f0 = *reinterpret_cast<float4*>(&pf[qq * 2]);
                const float4 f1 = *reinterpret_cast<float4*>(&pf[qq * 2 + 1]);
                float e[8];
                e[0] = __expf(f0.x); e[1] = __expf(f0.y);
                e[2] = __expf(f0.z); e[3] = __expf(f0.w);
                e[4] = __expf(f1.x); e[5] = __expf(f1.y);
                e[6] = __expf(f1.z); e[7] = __expf(f1.w);
                ls += (e[0] + e[1]) + (e[2] + e[3]) +
                      (e[4] + e[5]) + (e[6] + e[7]);
                uint32_t hw[4], lw[4];
                #pragma unroll
                for (int p = 0; p < 4; ++p)
                    split_pair(e[2 * p], e[2 * p + 1], hw[p], lw[p]);
                *(uint4*)(ab + asw[qq]) = make_uint4(hw[0], hw[1], hw[2], hw[3]);
                *(uint4*)(ab + 16384 + asw[qq]) =
                    make_uint4(lw[0], lw[1], lw[2], lw[3]);
            }
        }

        if (t + 1 < 32) {
            const int k0 = (t + 1) << 6;
            #pragma unroll
            for (int q = 0; q < 8; ++q)
                pf[q] = *(const uint4*)(sp + k0 + q * 4);
        }

        if (t + 1 < 32) CP_WAIT1(); else CP_WAIT0();
        __syncthreads();

        const uint32_t Abase = sb + st * 32768;
        const uint32_t Bbase = sb + 65536 + st * 32768;
        #pragma unroll
        for (int ks = 0; ks < 4; ++ks) {
            uint32_t ah[4][4], alr[4][4], bh[4][2], bl[4][2];
            #pragma unroll
            for (int i = 0; i < 4; ++i) {
                const uint32_t off = aro[i] +
                    ((uint32_t)(((ks << 1) | ach) ^ sx) << 4);
                ldsm4(ah[i],  Abase + off);
                ldsm4(alr[i], Abase + 16384 + off);
            }
            #pragma unroll
            for (int j2 = 0; j2 < 2; ++j2) {
                const uint32_t off = bro[j2] +
                    ((uint32_t)(((ks << 1) | bch) ^ sx) << 4);
                uint32_t r[4], r2[4];
                ldsm4(r,  Bbase + off);
                ldsm4(r2, Bbase + 16384 + off);
                bh[j2 * 2][0] = r[0];  bh[j2 * 2][1] = r[1];
                bh[j2 * 2 + 1][0] = r[2];  bh[j2 * 2 + 1][1] = r[3];
                bl[j2 * 2][0] = r2[0]; bl[j2 * 2][1] = r2[1];
                bl[j2 * 2 + 1][0] = r2[2]; bl[j2 * 2 + 1][1] = r2[3];
            }
            #pragma unroll
            for (int i = 0; i < 4; ++i)
                #pragma unroll
                for (int j = 0; j < 4; ++j) {
                    mma16816(acc[i][j], ah[i],  bh[j]);
                    mma16816(acc[i][j], alr[i], bh[j]);
                    mma16816(acc[i][j], ah[i],  bl[j]);
                }
        }
        __syncthreads();
    }

    lsm[tid] = ls;
    __syncthreads();

    const int erowl = wm * 64 + (lane >> 2);
    const int ecol = wn * 32 + (lane & 3) * 2;
    #pragma unroll
    for (int i = 0; i < 4; ++i) {
        const int r0 = erowl + i * 16;
        const int r1 = r0 + 8;
        const float inv0 = 1.0f / (lsm[2 * r0] + lsm[2 * r0 + 1]);
        const float inv1 = 1.0f / (lsm[2 * r1] + lsm[2 * r1 + 1]);
        #pragma unroll
        for (int j = 0; j < 4; ++j) {
            const int c = ecol + j * 8;
            const long long o0 = cbase + (long long)(m0 + r0) * ND + c;
            const long long o1 = cbase + (long long)(m0 + r1) * ND + c;
            uint32_t hp, lp;
            split_pair(acc[i][j][0] * inv0, acc[i][j][1] * inv0, hp, lp);
            *(uint32_t*)(Ch + o0) = hp;
            *(uint32_t*)(Cl + o0) = lp;
            split_pair(acc[i][j][2] * inv1, acc[i][j][3] * inv1, hp, lp);
            *(uint32_t*)(Ch + o1) = hp;
            *(uint32_t*)(Cl + o1) = lp;
        }
    }
}

// ---------------------------------------------------------------------------
// fp32 -> split bf16 (elementwise)
// ---------------------------------------------------------------------------
__global__ void __launch_bounds__(256) split_k(const float* __restrict__ in,
                                               __nv_bfloat16* __restrict__ oh,
                                               __nv_bfloat16* __restrict__ ol,
                                               long long n)
{
    for (long long i = blockIdx.x * 256ll + threadIdx.x; i < n;
         i += (long long)gridDim.x * 256) {
        __nv_bfloat16 h, l;
        split2(in[i], h, l);
        oh[i] = h; ol[i] = l;
    }
}

// ---------------------------------------------------------------------------
// transpose + split (generic, z-batched over one tensor)
// ---------------------------------------------------------------------------
__global__ void __launch_bounds__(256) tsplit_k(const float* __restrict__ in,
                                                __nv_bfloat16* __restrict__ oh,
                                                __nv_bfloat16* __restrict__ ol,
                                                int R, int C,
                                                long long inB, long long outB)
{
    __shared__ float t[32][33];
    const int b = blockIdx.z;
    in += b * inB; oh += b * outB; ol += b * outB;
    const int x = blockIdx.x * 32 + threadIdx.x;
    const int y0 = blockIdx.y * 32;
    #pragma unroll
    for (int i = 0; i < 4; ++i)
        t[threadIdx.y + i * 8][threadIdx.x] =
            in[(long long)(y0 + threadIdx.y + i * 8) * C + x];
    __syncthreads();
    const int ox = y0 + threadIdx.x;
    const int oy = blockIdx.x * 32;
    #pragma unroll
    for (int i = 0; i < 4; ++i) {
        const float v = t[threadIdx.x][threadIdx.y + i * 8];
        __nv_bfloat16 h, l;
        split2(v, h, l);
        const long long o = (long long)(oy + threadIdx.y + i * 8) * R + ox;
        oh[o] = h; ol[o] = l;
    }
}

// transpose + split all 4 weight matrices in ONE launch (z = which weight)
__global__ void __launch_bounds__(256) tsplit_w4(
    const float* __restrict__ in0, const float* __restrict__ in1,
    const float* __restrict__ in2, const float* __restrict__ in3,
    __nv_bfloat16* __restrict__ oh, __nv_bfloat16* __restrict__ ol)
{
    __shared__ float t[32][33];
    const int b = blockIdx.z;
    const float* in = (b == 0) ? in0 : (b == 1) ? in1 : (b == 2) ? in2 : in3;
    const long long ob = (long long)b * ND * ND;
    oh += ob; ol += ob;
    const int x = blockIdx.x * 32 + threadIdx.x;
    const int y0 = blockIdx.y * 32;
    #pragma unroll
    for (int i = 0; i < 4; ++i)
        t[threadIdx.y + i * 8][threadIdx.x] =
            in[(long long)(y0 + threadIdx.y + i * 8) * ND + x];
    __syncthreads();
    const int ox = y0 + threadIdx.x;
    const int oy = blockIdx.x * 32;
    #pragma unroll
    for (int i = 0; i < 4; ++i) {
        const float v = t[threadIdx.x][threadIdx.y + i * 8];
        __nv_bfloat16 h, l;
        split2(v, h, l);
        const long long o = (long long)(oy + threadIdx.y + i * 8) * ND + ox;
        oh[o] = h; ol[o] = l;
    }
}

// ---------------------------------------------------------------------------
extern "C" void kernel_launch(void* const* d_in, const int* in_sizes, int n_in,
                              void* d_out, int out_size)
{
    (void)in_sizes; (void)n_in; (void)out_size;
    const float* x  = (const float*)d_in[0];
    const float* Wq = (const float*)d_in[2];
    const float* bq = (const float*)d_in[3];
    const float* Wk = (const float*)d_in[4];
    const float* bk = (const float*)d_in[5];
    const float* Wv = (const float*)d_in[6];
    const float* bv = (const float*)d_in[7];
    const float* Wo = (const float*)d_in[8];
    const float* bo = (const float*)d_in[9];
    float* out = (float*)d_out;

    __nv_bfloat16 *xh, *xl, *wth, *wtl, *qh, *ql, *kh, *kl, *vth, *vtl;
    __nv_bfloat16 *oh, *ol;
    float *v32, *s32;
    cudaGetSymbolAddress((void**)&xh,  g_xh);
    cudaGetSymbolAddress((void**)&xl,  g_xl);
    cudaGetSymbolAddress((void**)&wth, g_wth);
    cudaGetSymbolAddress((void**)&wtl, g_wtl);
    cudaGetSymbolAddress((void**)&qh,  g_qh);
    cudaGetSymbolAddress((void**)&ql,  g_ql);
    cudaGetSymbolAddress((void**)&kh,  g_kh);
    cudaGetSymbolAddress((void**)&kl,  g_kl);
    cudaGetSymbolAddress((void**)&v32, g_v);
    cudaGetSymbolAddress((void**)&vth, g_vth);
    cudaGetSymbolAddress((void**)&vtl, g_vtl);
    cudaGetSymbolAddress((void**)&s32, g_s);
    cudaGetSymbolAddress((void**)&oh,  g_oh);
    cudaGetSymbolAddress((void**)&ol,  g_ol);

    cudaFuncSetAttribute(gemm_big<0>, cudaFuncAttributeMaxDynamicSharedMemorySize,
                         BIG_SMEM);
    cudaFuncSetAttribute(gemm_big<1>, cudaFuncAttributeMaxDynamicSharedMemorySize,
                         BIG_SMEM);
    cudaFuncSetAttribute(gemm_wm, cudaFuncAttributeMaxDynamicSharedMemorySize,
                         SMEM_BYTES);
    cudaFuncSetAttribute(pv_fused, cudaFuncAttributeMaxDynamicSharedMemorySize,
                         PV_SMEM);

    const long long sSD = (long long)NS * ND;
    const long long sSS = (long long)NS * NS;
    const long long WSZ = (long long)ND * ND;

    // launch 0: split x
    split_k<<<32768, 256>>>(x, xh, xl, (long long)TOK * ND);
    // launch 1: transpose+split all weights (one launch)
    {
        dim3 g(ND / 32, ND / 32, 4), b(32, 8, 1);
        tsplit_w4<<<g, b>>>(Wq, Wk, Wv, Wo, wth, wtl);
    }

    // launches 2-4: projections (512-thread 256x128 tiles)
    const dim3 gbig(ND / 128, TOK / 256, 1);
    gemm_big<1><<<gbig, 512, BIG_SMEM>>>(xh, xl, wth + 0 * WSZ, wtl + 0 * WSZ,
        bq, 1.0f, nullptr, qh, ql, ND);
    gemm_big<1><<<gbig, 512, BIG_SMEM>>>(xh, xl, wth + 1 * WSZ, wtl + 1 * WSZ,
        bk, 1.0f, nullptr, kh, kl, ND);
    gemm_big<0><<<gbig, 512, BIG_SMEM>>>(xh, xl, wth + 2 * WSZ, wtl + 2 * WSZ,
        bv, 1.0f, v32, nullptr, nullptr, ND);

    // launch 5 (ncu -s 5 profiles this): QK scores
    {
        dim3 g(NS / 128, NS / 128, NB * NH);
        gemm_wm<<<g, 256, SMEM_BYTES>>>(qh, ql, kh, kl, ATT_SCALE, s32,
            HD, ND, ND, NS, NH, sSD, HD, sSD, HD, (long long)NH * sSS, sSS);
    }

    // launch 6: transpose+split V per batch: [S,D] -> [D,S]
    {
        dim3 g(ND / 32, NS / 32, NB), b(32, 8, 1);
        tsplit_k<<<g, b>>>(v32, vth, vtl, NS, ND, sSD, sSD);
    }

    // launch 7: fused softmax + PV
    {
        dim3 g(1, NS / 128, NB * NH);
        pv_fused<<<g, 256, PV_SMEM>>>(s32, vth, vtl, oh, ol);
    }

    // launch 8: final projection -> d_out
    gemm_big<0><<<gbig, 512, BIG_SMEM>>>(oh, ol, wth + 3 * WSZ, wtl + 3 * WSZ,
        bo, 1.0f, out, nullptr, nullptr, ND);
}

// round 10
// speedup vs baseline: 1.3852x; 1.0980x over previous
#include <cuda_runtime.h>
#include <cuda_bf16.h>
#include <cstdint>

// Problem constants
#define NB 4
#define NS 2048
#define ND 2048
#define NH 16
#define HD 128
#define ATT_SCALE 0.08838834764831845f

// ---------------------------------------------------------------------------
// Scratch (device globals; allocation inside kernel_launch is forbidden)
// ---------------------------------------------------------------------------
#define TOK (NB * NS)                 // 8192 tokens
__device__ __align__(16) __nv_bfloat16 g_xh[TOK * ND];
__device__ __align__(16) __nv_bfloat16 g_xl[TOK * ND];
__device__ __align__(16) __nv_bfloat16 g_wth[4][ND * ND];   // W^T hi (q,k,v,o)
__device__ __align__(16) __nv_bfloat16 g_wtl[4][ND * ND];
__device__ __align__(16) __nv_bfloat16 g_qh[TOK * ND];
__device__ __align__(16) __nv_bfloat16 g_ql[TOK * ND];
__device__ __align__(16) __nv_bfloat16 g_kh[TOK * ND];
__device__ __align__(16) __nv_bfloat16 g_kl[TOK * ND];
__device__ __align__(16) float         g_v [TOK * ND];
__device__ __align__(16) __nv_bfloat16 g_vth[TOK * ND];     // V^T per batch [D][S]
__device__ __align__(16) __nv_bfloat16 g_vtl[TOK * ND];
__device__ __align__(16) float         g_s [(long long)NB * NH * NS * NS]; // 1 GB
__device__ __align__(16) __nv_bfloat16 g_oh[TOK * ND];
__device__ __align__(16) __nv_bfloat16 g_ol[TOK * ND];

// ---------------------------------------------------------------------------
// helpers
// ---------------------------------------------------------------------------
__device__ __forceinline__ uint32_t smem_u32(const void* p) {
    uint32_t a;
    asm("{ .reg .u64 t; cvta.to.shared.u64 t, %1; cvt.u32.u64 %0, t; }"
        : "=r"(a) : "l"(p));
    return a;
}
__device__ __forceinline__ void cpa16(uint32_t dst, const void* src) {
    asm volatile("cp.async.cg.shared.global [%0], [%1], 16;"
                 :: "r"(dst), "l"(src) : "memory");
}
#define CP_COMMIT() asm volatile("cp.async.commit_group;" ::: "memory")
#define CP_WAIT0()  asm volatile("cp.async.wait_group 0;" ::: "memory")
#define CP_WAIT1()  asm volatile("cp.async.wait_group 1;" ::: "memory")

__device__ __forceinline__ void ldsm4(uint32_t* r, uint32_t addr) {
    asm volatile("ldmatrix.sync.aligned.m8n8.x4.shared.b16 {%0,%1,%2,%3}, [%4];"
                 : "=r"(r[0]), "=r"(r[1]), "=r"(r[2]), "=r"(r[3]) : "r"(addr));
}
__device__ __forceinline__ void mma16816(float* d, const uint32_t* a,
                                         const uint32_t* b) {
    asm volatile(
        "mma.sync.aligned.m16n8k16.row.col.f32.bf16.bf16.f32 "
        "{%0,%1,%2,%3}, {%4,%5,%6,%7}, {%8,%9}, {%0,%1,%2,%3};"
        : "+f"(d[0]), "+f"(d[1]), "+f"(d[2]), "+f"(d[3])
        : "r"(a[0]), "r"(a[1]), "r"(a[2]), "r"(a[3]), "r"(b[0]), "r"(b[1]));
}
__device__ __forceinline__ void split2(float v, __nv_bfloat16& h, __nv_bfloat16& l) {
    h = __float2bfloat16(v);
    l = __float2bfloat16(v - __bfloat162float(h));
}
// pack (e0,e1) -> bf16x2 hi pair + lo (residual) pair; low half = e0
__device__ __forceinline__ void split_pair(float e0, float e1,
                                           uint32_t& hp, uint32_t& lp) {
    asm("cvt.rn.satfinite.bf16x2.f32 %0, %1, %2;" : "=r"(hp) : "f"(e1), "f"(e0));
    __nv_bfloat162 hb = *reinterpret_cast<__nv_bfloat162*>(&hp);
    const float l0 = e0 - __bfloat162float(hb.x);
    const float l1 = e1 - __bfloat162float(hb.y);
    asm("cvt.rn.satfinite.bf16x2.f32 %0, %1, %2;" : "=r"(lp) : "f"(l1), "f"(l0));
}

// ---------------------------------------------------------------------------
// gemm_128: 256 threads, __launch_bounds__(256,2) -> 2 CTAs/SM.
// Tile 128x128, K-chunk 32, 3 smem stages (32KB each, 96KB total), cp.async
// with 2-deep prefetch. Smem rows are 64B (32 bf16); swizzle: chunk ^= row[2:1]
// (off ^ ((off>>3)&0x30)) -> conflict-free ldmatrix phases.
// C[M,N] = alpha * A[M,K] * B[N,K]^T (+bias). Batched via blockIdx.z.
// OMODE 0: fp32 out; 1: split bf16 hi/lo out.
// stage layout: Ah @0 (8KB), Al @8192, Bh @16384, Bl @24576.
// ---------------------------------------------------------------------------
#define G128_SMEM (3 * 32768)

template <int OMODE>
__global__ void __launch_bounds__(256, 2) gemm_128(
    const __nv_bfloat16* __restrict__ Ah, const __nv_bfloat16* __restrict__ Al,
    const __nv_bfloat16* __restrict__ Bh, const __nv_bfloat16* __restrict__ Bl,
    const float* __restrict__ bias, float alpha,
    float* __restrict__ Cf, __nv_bfloat16* __restrict__ Ch,
    __nv_bfloat16* __restrict__ Cl,
    int K, int lda, int ldb, int ldc, int hdiv,
    long long sa1, long long sa2, long long sb1, long long sb2,
    long long sc1, long long sc2)
{
    extern __shared__ char smem[];
    const int tid = threadIdx.x;
    const uint32_t sb32 = smem_u32(smem);

    const int bz = blockIdx.z;
    const int zb = bz / hdiv;
    const int zh = bz - zb * hdiv;
    Ah += zb * sa1 + zh * sa2;  Al += zb * sa1 + zh * sa2;
    Bh += zb * sb1 + zh * sb2;  Bl += zb * sb1 + zh * sb2;
    const long long coff = zb * sc1 + zh * sc2;

    const int m0 = blockIdx.y * 128;
    const int n0 = blockIdx.x * 128;

    // ---- loader geometry: 512 16B-chunks per 8KB matrix-tile, 2 per thread
    long long aoff[2], boff[2];
    uint32_t ssw[2];
    #pragma unroll
    for (int q = 0; q < 2; ++q) {
        const int idx = tid + q * 256;
        const int row = idx >> 2;          // 0..127
        const int c16 = idx & 3;           // 16B chunk within 64B row
        aoff[q] = (long long)(m0 + row) * lda + c16 * 8;
        boff[q] = (long long)(n0 + row) * ldb + c16 * 8;
        const uint32_t bo = row * 64 + c16 * 16;
        ssw[q] = bo ^ ((bo >> 3) & 0x30);
    }

    // ---- warp compute geometry: 8 warps = 2(m) x 4(n); warp tile 64x32
    const int lane = tid & 31, warp = tid >> 5;
    const int wm = warp >> 2;
    const int wn = warp & 3;
    const int sx = lane & 7;
    const int am8 = (lane >> 3) & 1;
    const int ach = (lane >> 4) & 1;
    const int bn8 = (lane >> 4) & 1;
    const int bch = (lane >> 3) & 1;
    const uint32_t askewA = (uint32_t)(((sx) >> 1) & 3);   // row[2:1] (am8 -> bit3)
    uint32_t aro[4], bro[2];
    #pragma unroll
    for (int i = 0; i < 4; ++i)
        aro[i] = (uint32_t)(wm * 64 + i * 16 + sx + am8 * 8) * 64;
    #pragma unroll
    for (int j2 = 0; j2 < 2; ++j2)
        bro[j2] = (uint32_t)(wn * 32 + j2 * 16 + sx + bn8 * 8) * 64;

    float acc[4][4][4];
    #pragma unroll
    for (int i = 0; i < 4; ++i)
        #pragma unroll
        for (int j = 0; j < 4; ++j)
            #pragma unroll
            for (int e = 0; e < 4; ++e) acc[i][j][e] = 0.0f;

    const int nT = K >> 5;       // K-chunks of 32

    // ---- prologue: issue stages 0 and 1 as two groups
    #pragma unroll
    for (int s = 0; s < 2; ++s) {
        if (s < nT) {
            const uint32_t db = sb32 + s * 32768;
            const int kb = s << 5;
            #pragma unroll
            for (int q = 0; q < 2; ++q) {
                cpa16(db + 0     + ssw[q], Ah + aoff[q] + kb);
                cpa16(db + 8192  + ssw[q], Al + aoff[q] + kb);
                cpa16(db + 16384 + ssw[q], Bh + boff[q] + kb);
                cpa16(db + 24576 + ssw[q], Bl + boff[q] + kb);
            }
            CP_COMMIT();
        }
    }

    int stage = 0;
    for (int t = 0; t < nT; ++t) {
        // wait for chunk t's group (issued 2 iterations back)
        if (t + 1 < nT) CP_WAIT1(); else CP_WAIT0();
        __syncthreads();

        // issue chunk t+2 into the stage freed by chunk t-1
        if (t + 2 < nT) {
            const uint32_t db = sb32 + ((stage + 2) % 3) * 32768;
            const int kb = (t + 2) << 5;
            #pragma unroll
            for (int q = 0; q < 2; ++q) {
                cpa16(db + 0     + ssw[q], Ah + aoff[q] + kb);
                cpa16(db + 8192  + ssw[q], Al + aoff[q] + kb);
                cpa16(db + 16384 + ssw[q], Bh + boff[q] + kb);
                cpa16(db + 24576 + ssw[q], Bl + boff[q] + kb);
            }
            CP_COMMIT();
        }

        // compute chunk t
        const uint32_t Abase = sb32 + stage * 32768;
        const uint32_t Bbase = Abase + 16384;
        #pragma unroll
        for (int ks = 0; ks < 2; ++ks) {
            uint32_t ah[4][4], alr[4][4], bh[4][2], bl[4][2];
            const uint32_t kxa = ((uint32_t)(((ks << 1) | ach)) ^ askewA) << 4;
            const uint32_t kxb = ((uint32_t)(((ks << 1) | bch)) ^ askewA) << 4;
            #pragma unroll
            for (int i = 0; i < 4; ++i) {
                ldsm4(ah[i],  Abase + aro[i] + kxa);
                ldsm4(alr[i], Abase + 8192 + aro[i] + kxa);
            }
            #pragma unroll
            for (int j2 = 0; j2 < 2; ++j2) {
                uint32_t r[4], r2[4];
                ldsm4(r,  Bbase + bro[j2] + kxb);
                ldsm4(r2, Bbase + 8192 + bro[j2] + kxb);
                bh[j2 * 2][0] = r[0];  bh[j2 * 2][1] = r[1];
                bh[j2 * 2 + 1][0] = r[2];  bh[j2 * 2 + 1][1] = r[3];
                bl[j2 * 2][0] = r2[0]; bl[j2 * 2][1] = r2[1];
                bl[j2 * 2 + 1][0] = r2[2]; bl[j2 * 2 + 1][1] = r2[3];
            }
            #pragma unroll
            for (int i = 0; i < 4; ++i)
                #pragma unroll
                for (int j = 0; j < 4; ++j) {
                    mma16816(acc[i][j], ah[i],  bh[j]);
                    mma16816(acc[i][j], alr[i], bh[j]);
                    mma16816(acc[i][j], ah[i],  bl[j]);
                }
        }
        stage = (stage + 1) % 3;
        // NOTE: next iteration's __syncthreads (after its wait) is the barrier
        // that protects the stage this iteration just consumed.
    }

    // ---- epilogue ----
    const int erow = m0 + wm * 64 + (lane >> 2);
    const int ecol = n0 + wn * 32 + (lane & 3) * 2;
    #pragma unroll
    for (int j = 0; j < 4; ++j) {
        const int c = ecol + j * 8;
        const float b0 = (OMODE == 1 && bias) ? __ldg(bias + c)     :
                         (bias ? __ldg(bias + c)     : 0.0f);
        const float b1 = (OMODE == 1 && bias) ? __ldg(bias + c + 1) :
                         (bias ? __ldg(bias + c + 1) : 0.0f);
        #pragma unroll
        for (int i = 0; i < 4; ++i) {
            const long long r0 = erow + i * 16;
            const float v0 = acc[i][j][0] * alpha + b0;
            const float v1 = acc[i][j][1] * alpha + b1;
            const float v2 = acc[i][j][2] * alpha + b0;
            const float v3 = acc[i][j][3] * alpha + b1;
            const long long o0 = coff + r0 * ldc + c;
            const long long o1 = o0 + 8ll * ldc;
            if (OMODE == 0) {
                *(float2*)(Cf + o0) = make_float2(v0, v1);
                *(float2*)(Cf + o1) = make_float2(v2, v3);
            } else {
                uint32_t hp, lp;
                split_pair(v0, v1, hp, lp);
                *(uint32_t*)(Ch + o0) = hp;
                *(uint32_t*)(Cl + o0) = lp;
                split_pair(v2, v3, hp, lp);
                *(uint32_t*)(Ch + o1) = hp;
                *(uint32_t*)(Cl + o1) = lp;
            }
        }
    }
}

// ---------------------------------------------------------------------------
// Fused softmax + PV (proven round 5; unchanged)
// ---------------------------------------------------------------------------
#define PV_SMEM (131072 + 1024)

__global__ void __launch_bounds__(256, 1) pv_fused(
    const float* __restrict__ S,
    const __nv_bfloat16* __restrict__ Vh, const __nv_bfloat16* __restrict__ Vl,
    __nv_bfloat16* __restrict__ Ch, __nv_bfloat16* __restrict__ Cl)
{
    extern __shared__ char smem[];
    const int tid = threadIdx.x;
    const uint32_t sb = smem_u32(smem);
    float* lsm = (float*)(smem + 131072);

    const int bz = blockIdx.z;
    const int zb = bz >> 4, zh = bz & 15;
    S += (long long)bz * NS * NS;
    const long long vbase = (long long)zb * NS * ND + (long long)zh * HD * NS;
    Vh += vbase; Vl += vbase;
    const long long cbase = (long long)zb * NS * ND + zh * HD;

    const int m0 = blockIdx.y * 128;

    const int crow = tid >> 1, chalf = tid & 1;
    const float* sp = S + (long long)(m0 + crow) * NS + chalf * 32;
    uint32_t asw[4];
    #pragma unroll
    for (int q = 0; q < 4; ++q) {
        const uint32_t bo = crow * 128 + chalf * 64 + q * 16;
        asw[q] = bo ^ ((bo >> 3) & 0x70);
    }

    const int rb = tid >> 3, cc8 = (tid & 7) * 8;
    long long boff[4];
    uint32_t swo[4];
    #pragma unroll
    for (int j = 0; j < 4; ++j) {
        const int row = j * 32 + rb;
        boff[j] = (long long)row * NS + cc8;
        const uint32_t bo = row * 128 + (tid & 7) * 16;
        swo[j] = bo ^ ((bo >> 3) & 0x70);
    }

    const int lane = tid & 31, warp = tid >> 5;
    const int wm = warp >> 2, wn = warp & 3;
    const int sx = lane & 7;
    const int am8 = (lane >> 3) & 1, ach = (lane >> 4) & 1;
    const int bn8 = (lane >> 4) & 1, bch = (lane >> 3) & 1;
    uint32_t aro[4], bro[2];
    #pragma unroll
    for (int i = 0; i < 4; ++i)
        aro[i] = (uint32_t)(wm * 64 + i * 16 + sx + am8 * 8) * 128;
    #pragma unroll
    for (int j2 = 0; j2 < 2; ++j2)
        bro[j2] = (uint32_t)(wn * 32 + j2 * 16 + sx + bn8 * 8) * 128;

    float acc[4][4][4];
    #pragma unroll
    for (int i = 0; i < 4; ++i)
        #pragma unroll
        for (int j = 0; j < 4; ++j)
            #pragma unroll
            for (int e = 0; e < 4; ++e) acc[i][j][e] = 0.0f;

    float ls = 0.0f;
    uint4 pf[8];
    #pragma unroll
    for (int q = 0; q < 8; ++q) pf[q] = *(const uint4*)(sp + q * 4);
    {
        const uint32_t db = sb + 65536;
        #pragma unroll
        for (int j = 0; j < 4; ++j) {
            cpa16(db + swo[j],         Vh + boff[j]);
            cpa16(db + 16384 + swo[j], Vl + boff[j]);
        }
        CP_COMMIT();
    }

    for (int t = 0; t < 32; ++t) {
        const int st = t & 1;
        if (t + 1 < 32) {
            const uint32_t db = sb + 65536 + ((t + 1) & 1) * 32768;
            const int k0 = (t + 1) << 6;
            #pragma unroll
            for (int j = 0; j < 4; ++j) {
                cpa16(db + swo[j],         Vh + boff[j] + k0);
                cpa16(db + 16384 + swo[j], Vl + boff[j] + k0);
            }
            CP_COMMIT();
        }

        {
            char* ab = smem + st * 32768;
            #pragma unroll
            for (int qq = 0; qq < 4; ++qq) {
                const float4 f0 = *reinterpret_cast<float4*>(&pf[qq * 2]);
                const float4 f1 = *reinterpret_cast<float4*>(&pf[qq * 2 + 1]);
                float e[8];
                e[0] = __expf(f0.x); e[1] = __expf(f0.y);
                e[2] = __expf(f0.z); e[3] = __expf(f0.w);
                e[4] = __expf(f1.x); e[5] = __expf(f1.y);
                e[6] = __expf(f1.z); e[7] = __expf(f1.w);
                ls += (e[0] + e[1]) + (e[2] + e[3]) +
                      (e[4] + e[5]) + (e[6] + e[7]);
                uint32_t hw[4], lw[4];
                #pragma unroll
                for (int p = 0; p < 4; ++p)
                    split_pair(e[2 * p], e[2 * p + 1], hw[p], lw[p]);
                *(uint4*)(ab + asw[qq]) = make_uint4(hw[0], hw[1], hw[2], hw[3]);
                *(uint4*)(ab + 16384 + asw[qq]) =
                    make_uint4(lw[0], lw[1], lw[2], lw[3]);
            }
        }

        if (t + 1 < 32) {
            const int k0 = (t + 1) << 6;
            #pragma unroll
            for (int q = 0; q < 8; ++q)
                pf[q] = *(const uint4*)(sp + k0 + q * 4);
        }

        if (t + 1 < 32) CP_WAIT1(); else CP_WAIT0();
        __syncthreads();

        const uint32_t Abase = sb + st * 32768;
        const uint32_t Bbase = sb + 65536 + st * 32768;
        #pragma unroll
        for (int ks = 0; ks < 4; ++ks) {
            uint32_t ah[4][4], alr[4][4], bh[4][2], bl[4][2];
            #pragma unroll
            for (int i = 0; i < 4; ++i) {
                const uint32_t off = aro[i] +
                    ((uint32_t)(((ks << 1) | ach) ^ sx) << 4);
                ldsm4(ah[i],  Abase + off);
                ldsm4(alr[i], Abase + 16384 + off);
            }
            #pragma unroll
            for (int j2 = 0; j2 < 2; ++j2) {
                const uint32_t off = bro[j2] +
                    ((uint32_t)(((ks << 1) | bch) ^ sx) << 4);
                uint32_t r[4], r2[4];
                ldsm4(r,  Bbase + off);
                ldsm4(r2, Bbase + 16384 + off);
                bh[j2 * 2][0] = r[0];  bh[j2 * 2][1] = r[1];
                bh[j2 * 2 + 1][0] = r[2];  bh[j2 * 2 + 1][1] = r[3];
                bl[j2 * 2][0] = r2[0]; bl[j2 * 2][1] = r2[1];
                bl[j2 * 2 + 1][0] = r2[2]; bl[j2 * 2 + 1][1] = r2[3];
            }
            #pragma unroll
            for (int i = 0; i < 4; ++i)
                #pragma unroll
                for (int j = 0; j < 4; ++j) {
                    mma16816(acc[i][j], ah[i],  bh[j]);
                    mma16816(acc[i][j], alr[i], bh[j]);
                    mma16816(acc[i][j], ah[i],  bl[j]);
                }
        }
        __syncthreads();
    }

    lsm[tid] = ls;
    __syncthreads();

    const int erowl = wm * 64 + (lane >> 2);
    const int ecol = wn * 32 + (lane & 3) * 2;
    #pragma unroll
    for (int i = 0; i < 4; ++i) {
        const int r0 = erowl + i * 16;
        const int r1 = r0 + 8;
        const float inv0 = 1.0f / (lsm[2 * r0] + lsm[2 * r0 + 1]);
        const float inv1 = 1.0f / (lsm[2 * r1] + lsm[2 * r1 + 1]);
        #pragma unroll
        for (int j = 0; j < 4; ++j) {
            const int c = ecol + j * 8;
            const long long o0 = cbase + (long long)(m0 + r0) * ND + c;
            const long long o1 = cbase + (long long)(m0 + r1) * ND + c;
            uint32_t hp, lp;
            split_pair(acc[i][j][0] * inv0, acc[i][j][1] * inv0, hp, lp);
            *(uint32_t*)(Ch + o0) = hp;
            *(uint32_t*)(Cl + o0) = lp;
            split_pair(acc[i][j][2] * inv1, acc[i][j][3] * inv1, hp, lp);
            *(uint32_t*)(Ch + o1) = hp;
            *(uint32_t*)(Cl + o1) = lp;
        }
    }
}

// ---------------------------------------------------------------------------
// fp32 -> split bf16 (elementwise)
// ---------------------------------------------------------------------------
__global__ void __launch_bounds__(256) split_k(const float* __restrict__ in,
                                               __nv_bfloat16* __restrict__ oh,
                                               __nv_bfloat16* __restrict__ ol,
                                               long long n)
{
    for (long long i = blockIdx.x * 256ll + threadIdx.x; i < n;
         i += (long long)gridDim.x * 256) {
        __nv_bfloat16 h, l;
        split2(in[i], h, l);
        oh[i] = h; ol[i] = l;
    }
}

// ---------------------------------------------------------------------------
// transpose + split (generic, z-batched over one tensor)
// ---------------------------------------------------------------------------
__global__ void __launch_bounds__(256) tsplit_k(const float* __restrict__ in,
                                                __nv_bfloat16* __restrict__ oh,
                                                __nv_bfloat16* __restrict__ ol,
                                                int R, int C,
                                                long long inB, long long outB)
{
    __shared__ float t[32][33];
    const int b = blockIdx.z;
    in += b * inB; oh += b * outB; ol += b * outB;
    const int x = blockIdx.x * 32 + threadIdx.x;
    const int y0 = blockIdx.y * 32;
    #pragma unroll
    for (int i = 0; i < 4; ++i)
        t[threadIdx.y + i * 8][threadIdx.x] =
            in[(long long)(y0 + threadIdx.y + i * 8) * C + x];
    __syncthreads();
    const int ox = y0 + threadIdx.x;
    const int oy = blockIdx.x * 32;
    #pragma unroll
    for (int i = 0; i < 4; ++i) {
        const float v = t[threadIdx.x][threadIdx.y + i * 8];
        __nv_bfloat16 h, l;
        split2(v, h, l);
        const long long o = (long long)(oy + threadIdx.y + i * 8) * R + ox;
        oh[o] = h; ol[o] = l;
    }
}

// transpose + split all 4 weight matrices in ONE launch (z = which weight)
__global__ void __launch_bounds__(256) tsplit_w4(
    const float* __restrict__ in0, const float* __restrict__ in1,
    const float* __restrict__ in2, const float* __restrict__ in3,
    __nv_bfloat16* __restrict__ oh, __nv_bfloat16* __restrict__ ol)
{
    __shared__ float t[32][33];
    const int b = blockIdx.z;
    const float* in = (b == 0) ? in0 : (b == 1) ? in1 : (b == 2) ? in2 : in3;
    const long long ob = (long long)b * ND * ND;
    oh += ob; ol += ob;
    const int x = blockIdx.x * 32 + threadIdx.x;
    const int y0 = blockIdx.y * 32;
    #pragma unroll
    for (int i = 0; i < 4; ++i)
        t[threadIdx.y + i * 8][threadIdx.x] =
            in[(long long)(y0 + threadIdx.y + i * 8) * ND + x];
    __syncthreads();
    const int ox = y0 + threadIdx.x;
    const int oy = blockIdx.x * 32;
    #pragma unroll
    for (int i = 0; i < 4; ++i) {
        const float v = t[threadIdx.x][threadIdx.y + i * 8];
        __nv_bfloat16 h, l;
        split2(v, h, l);
        const long long o = (long long)(oy + threadIdx.y + i * 8) * ND + ox;
        oh[o] = h; ol[o] = l;
    }
}

// ---------------------------------------------------------------------------
extern "C" void kernel_launch(void* const* d_in, const int* in_sizes, int n_in,
                              void* d_out, int out_size)
{
    (void)in_sizes; (void)n_in; (void)out_size;
    const float* x  = (const float*)d_in[0];
    const float* Wq = (const float*)d_in[2];
    const float* bq = (const float*)d_in[3];
    const float* Wk = (const float*)d_in[4];
    const float* bk = (const float*)d_in[5];
    const float* Wv = (const float*)d_in[6];
    const float* bv = (const float*)d_in[7];
    const float* Wo = (const float*)d_in[8];
    const float* bo = (const float*)d_in[9];
    float* out = (float*)d_out;

    __nv_bfloat16 *xh, *xl, *wth, *wtl, *qh, *ql, *kh, *kl, *vth, *vtl;
    __nv_bfloat16 *oh, *ol;
    float *v32, *s32;
    cudaGetSymbolAddress((void**)&xh,  g_xh);
    cudaGetSymbolAddress((void**)&xl,  g_xl);
    cudaGetSymbolAddress((void**)&wth, g_wth);
    cudaGetSymbolAddress((void**)&wtl, g_wtl);
    cudaGetSymbolAddress((void**)&qh,  g_qh);
    cudaGetSymbolAddress((void**)&ql,  g_ql);
    cudaGetSymbolAddress((void**)&kh,  g_kh);
    cudaGetSymbolAddress((void**)&kl,  g_kl);
    cudaGetSymbolAddress((void**)&v32, g_v);
    cudaGetSymbolAddress((void**)&vth, g_vth);
    cudaGetSymbolAddress((void**)&vtl, g_vtl);
    cudaGetSymbolAddress((void**)&s32, g_s);
    cudaGetSymbolAddress((void**)&oh,  g_oh);
    cudaGetSymbolAddress((void**)&ol,  g_ol);

    cudaFuncSetAttribute(gemm_128<0>, cudaFuncAttributeMaxDynamicSharedMemorySize,
                         G128_SMEM);
    cudaFuncSetAttribute(gemm_128<1>, cudaFuncAttributeMaxDynamicSharedMemorySize,
                         G128_SMEM);
    cudaFuncSetAttribute(pv_fused, cudaFuncAttributeMaxDynamicSharedMemorySize,
                         PV_SMEM);

    const long long sSD = (long long)NS * ND;
    const long long sSS = (long long)NS * NS;
    const long long WSZ = (long long)ND * ND;

    // launch 0: split x
    split_k<<<32768, 256>>>(x, xh, xl, (long long)TOK * ND);
    // launch 1: transpose+split all weights (one launch)
    {
        dim3 g(ND / 32, ND / 32, 4), b(32, 8, 1);
        tsplit_w4<<<g, b>>>(Wq, Wk, Wv, Wo, wth, wtl);
    }

    // launches 2-4: projections
    const dim3 gproj(ND / 128, TOK / 128, 1);
    gemm_128<1><<<gproj, 256, G128_SMEM>>>(xh, xl, wth + 0 * WSZ, wtl + 0 * WSZ,
        bq, 1.0f, nullptr, qh, ql, ND, ND, ND, ND, 1, 0, 0, 0, 0, 0, 0);
    gemm_128<1><<<gproj, 256, G128_SMEM>>>(xh, xl, wth + 1 * WSZ, wtl + 1 * WSZ,
        bk, 1.0f, nullptr, kh, kl, ND, ND, ND, ND, 1, 0, 0, 0, 0, 0, 0);
    gemm_128<0><<<gproj, 256, G128_SMEM>>>(xh, xl, wth + 2 * WSZ, wtl + 2 * WSZ,
        bv, 1.0f, v32, nullptr, nullptr, ND, ND, ND, ND, 1, 0, 0, 0, 0, 0, 0);

    // launch 5 (ncu -s 5 profiles this): QK scores
    {
        dim3 g(NS / 128, NS / 128, NB * NH);
        gemm_128<0><<<g, 256, G128_SMEM>>>(qh, ql, kh, kl, nullptr, ATT_SCALE,
            s32, nullptr, nullptr, HD, ND, ND, NS,
            NH, sSD, HD, sSD, HD, (long long)NH * sSS, sSS);
    }

    // launch 6: transpose+split V per batch: [S,D] -> [D,S]
    {
        dim3 g(ND / 32, NS / 32, NB), b(32, 8, 1);
        tsplit_k<<<g, b>>>(v32, vth, vtl, NS, ND, sSD, sSD);
    }

    // launch 7: fused softmax + PV
    {
        dim3 g(1, NS / 128, NB * NH);
        pv_fused<<<g, 256, PV_SMEM>>>(s32, vth, vtl, oh, ol);
    }

    // launch 8: final projection -> d_out
    gemm_128<0><<<gproj, 256, G128_SMEM>>>(oh, ol, wth + 3 * WSZ, wtl + 3 * WSZ,
        bo, 1.0f, out, nullptr, nullptr, ND, ND, ND, ND, 1, 0, 0, 0, 0, 0, 0);
}

// round 12
// speedup vs baseline: 1.7143x; 1.2376x over previous
#include <cuda_runtime.h>
#include <cuda_fp16.h>
#include <cstdint>

// Problem constants
#define NB 4
#define NS 2048
#define ND 2048
#define NH 16
#define HD 128
#define ATT_SCALE 0.08838834764831845f

// ---------------------------------------------------------------------------
// Scratch (device globals; allocation inside kernel_launch is forbidden)
// ---------------------------------------------------------------------------
#define TOK (NB * NS)                 // 8192 tokens
__device__ __align__(16) __half g_xh[TOK * ND];
__device__ __align__(16) __half g_xl[TOK * ND];
__device__ __align__(16) __half g_wth[4][ND * ND];          // W^T hi only
__device__ __align__(16) __half g_qh[TOK * ND];
__device__ __align__(16) __half g_ql[TOK * ND];
__device__ __align__(16) __half g_kh[TOK * ND];
__device__ __align__(16) __half g_kl[TOK * ND];
__device__ __align__(16) float  g_v [TOK * ND];
__device__ __align__(16) __half g_vth[TOK * ND];            // V^T per batch [D][S]
__device__ __align__(16) __half g_vtl[TOK * ND];
__device__ __align__(16) __half g_ph[(long long)NB * NH * NS * NS]; // 512 MB
__device__ __align__(16) __half g_pl[(long long)NB * NH * NS * NS]; // 512 MB
__device__ __align__(16) float  g_l [NB * NH * NS];         // row sums of exp
__device__ __align__(16) __half g_oh[TOK * ND];
__device__ __align__(16) __half g_ol[TOK * ND];

// ---------------------------------------------------------------------------
// helpers
// ---------------------------------------------------------------------------
__device__ __forceinline__ uint32_t smem_u32(const void* p) {
    uint32_t a;
    asm("{ .reg .u64 t; cvta.to.shared.u64 t, %1; cvt.u32.u64 %0, t; }"
        : "=r"(a) : "l"(p));
    return a;
}
__device__ __forceinline__ void cpa16(uint32_t dst, const void* src) {
    asm volatile("cp.async.cg.shared.global [%0], [%1], 16;"
                 :: "r"(dst), "l"(src) : "memory");
}
#define CP_COMMIT() asm volatile("cp.async.commit_group;" ::: "memory")
#define CP_WAIT0()  asm volatile("cp.async.wait_group 0;" ::: "memory")
#define CP_WAIT1()  asm volatile("cp.async.wait_group 1;" ::: "memory")

__device__ __forceinline__ void ldsm4(uint32_t* r, uint32_t addr) {
    asm volatile("ldmatrix.sync.aligned.m8n8.x4.shared.b16 {%0,%1,%2,%3}, [%4];"
                 : "=r"(r[0]), "=r"(r[1]), "=r"(r[2]), "=r"(r[3]) : "r"(addr));
}
__device__ __forceinline__ void mma16816(float* d, const uint32_t* a,
                                         const uint32_t* b) {
    asm volatile(
        "mma.sync.aligned.m16n8k16.row.col.f32.f16.f16.f32 "
        "{%0,%1,%2,%3}, {%4,%5,%6,%7}, {%8,%9}, {%0,%1,%2,%3};"
        : "+f"(d[0]), "+f"(d[1]), "+f"(d[2]), "+f"(d[3])
        : "r"(a[0]), "r"(a[1]), "r"(a[2]), "r"(a[3]), "r"(b[0]), "r"(b[1]));
}
__device__ __forceinline__ void split2h(float v, __half& h, __half& l) {
    h = __float2half(v);
    l = __float2half(v - __half2float(h));
}
// pack (e0,e1) -> f16x2 hi pair + lo (residual) pair; low half = e0
__device__ __forceinline__ void split_pair(float e0, float e1,
                                           uint32_t& hp, uint32_t& lp) {
    asm("cvt.rn.f16x2.f32 %0, %1, %2;" : "=r"(hp) : "f"(e1), "f"(e0));
    __half2 hb = *reinterpret_cast<__half2*>(&hp);
    const float l0 = e0 - __half2float(hb.x);
    const float l1 = e1 - __half2float(hb.y);
    asm("cvt.rn.f16x2.f32 %0, %1, %2;" : "=r"(lp) : "f"(l1), "f"(l0));
}

// ---------------------------------------------------------------------------
// gemm_u: unified 2-CTA/SM tensor-core GEMM, 256 threads, tile 128x128,
// K-chunk 32, 3 smem stages, cp.async 2-deep prefetch, 64B-row swizzle.
// C[M,N] = A[M,K] * B[N,K]^T, A = Ah+Al (exact fp16 split).
// NPROD 2: C = (Ah+Al)*Bh     (B single fp16; no Bl traffic/MMA)
// NPROD 3: C = AhBh + AlBh + AhBl  (both split; residual ~2^-21)
// OMODE 0: Cf = alpha*acc + bias (fp32)
// OMODE 1: split fp16 out = alpha*acc + bias
// OMODE 2: P = exp(alpha*acc) split fp16 + atomic row-sums into lbuf
// OMODE 3: split fp16 out = acc / lbuf[row]
// stage: Ah@0 Al@8192 Bh@16384 [Bl@24576]; stage size 32KB (3P) / 24KB (2P)
// ---------------------------------------------------------------------------
template <int NPROD, int OMODE>
__global__ void __launch_bounds__(256, 2) gemm_u(
    const __half* __restrict__ Ah, const __half* __restrict__ Al,
    const __half* __restrict__ Bh, const __half* __restrict__ Bl,
    const float* __restrict__ bias, float* __restrict__ lbuf,
    float alpha,
    float* __restrict__ Cf, __half* __restrict__ Ch, __half* __restrict__ Cl,
    int K, int lda, int ldb, int ldc, int hdiv,
    long long sa1, long long sa2, long long sb1, long long sb2,
    long long sc1, long long sc2, int lstride)
{
    constexpr uint32_t STAGE = (NPROD == 3) ? 32768u : 24576u;
    extern __shared__ char smem[];
    const int tid = threadIdx.x;
    const uint32_t sb32 = smem_u32(smem);

    const int bz = blockIdx.z;
    const int zb = bz / hdiv;
    const int zh = bz - zb * hdiv;
    Ah += zb * sa1 + zh * sa2;  Al += zb * sa1 + zh * sa2;
    Bh += zb * sb1 + zh * sb2;
    if (NPROD == 3) Bl += zb * sb1 + zh * sb2;
    const long long coff = zb * sc1 + zh * sc2;
    const long long loff = (long long)bz * lstride;

    const int m0 = blockIdx.y * 128;
    const int n0 = blockIdx.x * 128;

    // loader geometry: 512 16B-chunks per 8KB matrix-tile, 2 per thread
    long long aoff[2], boff[2];
    uint32_t ssw[2];
    #pragma unroll
    for (int q = 0; q < 2; ++q) {
        const int idx = tid + q * 256;
        const int row = idx >> 2;
        const int c16 = idx & 3;
        aoff[q] = (long long)(m0 + row) * lda + c16 * 8;
        boff[q] = (long long)(n0 + row) * ldb + c16 * 8;
        const uint32_t bo = row * 64 + c16 * 16;
        ssw[q] = bo ^ ((bo >> 3) & 0x30);
    }

    // warp compute geometry: 8 warps = 2(m) x 4(n); warp tile 64x32
    const int lane = tid & 31, warp = tid >> 5;
    const int wm = warp >> 2;
    const int wn = warp & 3;
    const int sx = lane & 7;
    const int am8 = (lane >> 3) & 1;
    const int ach = (lane >> 4) & 1;
    const int bn8 = (lane >> 4) & 1;
    const int bch = (lane >> 3) & 1;
    const uint32_t askewA = (uint32_t)((sx >> 1) & 3);
    uint32_t aro[4], bro[2];
    #pragma unroll
    for (int i = 0; i < 4; ++i)
        aro[i] = (uint32_t)(wm * 64 + i * 16 + sx + am8 * 8) * 64;
    #pragma unroll
    for (int j2 = 0; j2 < 2; ++j2)
        bro[j2] = (uint32_t)(wn * 32 + j2 * 16 + sx + bn8 * 8) * 64;

    float acc[4][4][4];
    #pragma unroll
    for (int i = 0; i < 4; ++i)
        #pragma unroll
        for (int j = 0; j < 4; ++j)
            #pragma unroll
            for (int e = 0; e < 4; ++e) acc[i][j][e] = 0.0f;

    const int nT = K >> 5;

    // prologue: issue stages 0 and 1
    #pragma unroll
    for (int s = 0; s < 2; ++s) {
        if (s < nT) {
            const uint32_t db = sb32 + s * STAGE;
            const int kb = s << 5;
            #pragma unroll
            for (int q = 0; q < 2; ++q) {
                cpa16(db + 0     + ssw[q], Ah + aoff[q] + kb);
                cpa16(db + 8192  + ssw[q], Al + aoff[q] + kb);
                cpa16(db + 16384 + ssw[q], Bh + boff[q] + kb);
                if (NPROD == 3)
                    cpa16(db + 24576 + ssw[q], Bl + boff[q] + kb);
            }
            CP_COMMIT();
        }
    }

    int stage = 0;
    for (int t = 0; t < nT; ++t) {
        if (t + 1 < nT) CP_WAIT1(); else CP_WAIT0();
        __syncthreads();

        if (t + 2 < nT) {
            const uint32_t db = sb32 + ((stage + 2) % 3) * STAGE;
            const int kb = (t + 2) << 5;
            #pragma unroll
            for (int q = 0; q < 2; ++q) {
                cpa16(db + 0     + ssw[q], Ah + aoff[q] + kb);
                cpa16(db + 8192  + ssw[q], Al + aoff[q] + kb);
                cpa16(db + 16384 + ssw[q], Bh + boff[q] + kb);
                if (NPROD == 3)
                    cpa16(db + 24576 + ssw[q], Bl + boff[q] + kb);
            }
            CP_COMMIT();
        }

        const uint32_t Abase = sb32 + stage * STAGE;
        const uint32_t Bbase = Abase + 16384;
        #pragma unroll
        for (int ks = 0; ks < 2; ++ks) {
            uint32_t ah[4][4], alr[4][4], bh[4][2], bl[4][2];
            const uint32_t kxa = ((uint32_t)(((ks << 1) | ach)) ^ askewA) << 4;
            const uint32_t kxb = ((uint32_t)(((ks << 1) | bch)) ^ askewA) << 4;
            #pragma unroll
            for (int i = 0; i < 4; ++i) {
                ldsm4(ah[i],  Abase + aro[i] + kxa);
                ldsm4(alr[i], Abase + 8192 + aro[i] + kxa);
            }
            #pragma unroll
            for (int j2 = 0; j2 < 2; ++j2) {
                uint32_t r[4];
                ldsm4(r, Bbase + bro[j2] + kxb);
                bh[j2 * 2][0] = r[0];  bh[j2 * 2][1] = r[1];
                bh[j2 * 2 + 1][0] = r[2];  bh[j2 * 2 + 1][1] = r[3];
                if (NPROD == 3) {
                    uint32_t r2[4];
                    ldsm4(r2, Bbase + 8192 + bro[j2] + kxb);
                    bl[j2 * 2][0] = r2[0]; bl[j2 * 2][1] = r2[1];
                    bl[j2 * 2 + 1][0] = r2[2]; bl[j2 * 2 + 1][1] = r2[3];
                }
            }
            #pragma unroll
            for (int i = 0; i < 4; ++i)
                #pragma unroll
                for (int j = 0; j < 4; ++j) {
                    mma16816(acc[i][j], ah[i],  bh[j]);
                    mma16816(acc[i][j], alr[i], bh[j]);
                    if (NPROD == 3)
                        mma16816(acc[i][j], ah[i], bl[j]);
                }
        }
        stage = (stage + 1) % 3;
    }

    // ---- epilogue ----
    const int erow = m0 + wm * 64 + (lane >> 2);   // row within batch slice
    const int ecol = n0 + wn * 32 + (lane & 3) * 2;

    if (OMODE == 2) {
        // P = exp(alpha*acc) split fp16 + atomic row sums
        float rsum[4][2];
        #pragma unroll
        for (int i = 0; i < 4; ++i) { rsum[i][0] = 0.0f; rsum[i][1] = 0.0f; }
        #pragma unroll
        for (int j = 0; j < 4; ++j) {
            const int c = ecol + j * 8;
            #pragma unroll
            for (int i = 0; i < 4; ++i) {
                const float e0 = __expf(acc[i][j][0] * alpha);
                const float e1 = __expf(acc[i][j][1] * alpha);
                const float e2 = __expf(acc[i][j][2] * alpha);
                const float e3 = __expf(acc[i][j][3] * alpha);
                rsum[i][0] += e0 + e1;
                rsum[i][1] += e2 + e3;
                const long long o0 = coff + (long long)(erow + i * 16) * ldc + c;
                const long long o1 = o0 + 8ll * ldc;
                uint32_t hp, lp;
                split_pair(e0, e1, hp, lp);
                *(uint32_t*)(Ch + o0) = hp;
                *(uint32_t*)(Cl + o0) = lp;
                split_pair(e2, e3, hp, lp);
                *(uint32_t*)(Ch + o1) = hp;
                *(uint32_t*)(Cl + o1) = lp;
            }
        }
        #pragma unroll
        for (int i = 0; i < 4; ++i)
            #pragma unroll
            for (int par = 0; par < 2; ++par) {
                float v = rsum[i][par];
                v += __shfl_xor_sync(0xffffffffu, v, 1);
                v += __shfl_xor_sync(0xffffffffu, v, 2);
                if ((lane & 3) == 0)
                    atomicAdd(lbuf + loff + erow + i * 16 + par * 8, v);
            }
        return;
    }

    #pragma unroll
    for (int j = 0; j < 4; ++j) {
        const int c = ecol + j * 8;
        float b0 = 0.0f, b1 = 0.0f;
        if (OMODE == 0 || OMODE == 1) {
            b0 = bias ? __ldg(bias + c)     : 0.0f;
            b1 = bias ? __ldg(bias + c + 1) : 0.0f;
        }
        #pragma unroll
        for (int i = 0; i < 4; ++i) {
            float s0 = alpha, s1 = alpha;
            if (OMODE == 3) {
                s0 = 1.0f / __ldg(lbuf + loff + erow + i * 16);
                s1 = 1.0f / __ldg(lbuf + loff + erow + i * 16 + 8);
            }
            const float v0 = acc[i][j][0] * s0 + b0;
            const float v1 = acc[i][j][1] * s0 + b1;
            const float v2 = acc[i][j][2] * s1 + b0;
            const float v3 = acc[i][j][3] * s1 + b1;
            const long long o0 = coff + (long long)(erow + i * 16) * ldc + c;
            const long long o1 = o0 + 8ll * ldc;
            if (OMODE == 0) {
                *(float2*)(Cf + o0) = make_float2(v0, v1);
                *(float2*)(Cf + o1) = make_float2(v2, v3);
            } else {
                uint32_t hp, lp;
                split_pair(v0, v1, hp, lp);
                *(uint32_t*)(Ch + o0) = hp;
                *(uint32_t*)(Cl + o0) = lp;
                split_pair(v2, v3, hp, lp);
                *(uint32_t*)(Ch + o1) = hp;
                *(uint32_t*)(Cl + o1) = lp;
            }
        }
    }
}

// ---------------------------------------------------------------------------
// fp32 -> split fp16 (elementwise)
// ---------------------------------------------------------------------------
__global__ void __launch_bounds__(256) split_k(const float* __restrict__ in,
                                               __half* __restrict__ oh,
                                               __half* __restrict__ ol,
                                               long long n)
{
    for (long long i = blockIdx.x * 256ll + threadIdx.x; i < n;
         i += (long long)gridDim.x * 256) {
        __half h, l;
        split2h(in[i], h, l);
        oh[i] = h; ol[i] = l;
    }
}

// ---------------------------------------------------------------------------
// transpose + split fp16 hi/lo (z-batched)
// ---------------------------------------------------------------------------
__global__ void __launch_bounds__(256) tsplit_k(const float* __restrict__ in,
                                                __half* __restrict__ oh,
                                                __half* __restrict__ ol,
                                                int R, int C,
                                                long long inB, long long outB)
{
    __shared__ float t[32][33];
    const int b = blockIdx.z;
    in += b * inB; oh += b * outB; ol += b * outB;
    const int x = blockIdx.x * 32 + threadIdx.x;
    const int y0 = blockIdx.y * 32;
    #pragma unroll
    for (int i = 0; i < 4; ++i)
        t[threadIdx.y + i * 8][threadIdx.x] =
            in[(long long)(y0 + threadIdx.y + i * 8) * C + x];
    __syncthreads();
    const int ox = y0 + threadIdx.x;
    const int oy = blockIdx.x * 32;
    #pragma unroll
    for (int i = 0; i < 4; ++i) {
        const float v = t[threadIdx.x][threadIdx.y + i * 8];
        __half h, l;
        split2h(v, h, l);
        const long long o = (long long)(oy + threadIdx.y + i * 8) * R + ox;
        oh[o] = h; ol[o] = l;
    }
}

// transpose all 4 weight matrices, hi only (2-product B operand)
__global__ void __launch_bounds__(256) tsplit_w4(
    const float* __restrict__ in0, const float* __restrict__ in1,
    const float* __restrict__ in2, const float* __restrict__ in3,
    __half* __restrict__ oh)
{
    __shared__ float t[32][33];
    const int b = blockIdx.z;
    const float* in = (b == 0) ? in0 : (b == 1) ? in1 : (b == 2) ? in2 : in3;
    oh += (long long)b * ND * ND;
    const int x = blockIdx.x * 32 + threadIdx.x;
    const int y0 = blockIdx.y * 32;
    #pragma unroll
    for (int i = 0; i < 4; ++i)
        t[threadIdx.y + i * 8][threadIdx.x] =
            in[(long long)(y0 + threadIdx.y + i * 8) * ND + x];
    __syncthreads();
    const int oy = blockIdx.x * 32;
    const int ox = y0 + threadIdx.x;
    #pragma unroll
    for (int i = 0; i < 4; ++i) {
        const float v = t[threadIdx.x][threadIdx.y + i * 8];
        const long long o = (long long)(oy + threadIdx.y + i * 8) * ND + ox;
        oh[o] = __float2half(v);
    }
}

__global__ void __launch_bounds__(256) zero_l(float* __restrict__ l)
{
    const int i = blockIdx.x * 256 + threadIdx.x;
    ((float4*)l)[i] = make_float4(0.f, 0.f, 0.f, 0.f);
}

// ---------------------------------------------------------------------------
extern "C" void kernel_launch(void* const* d_in, const int* in_sizes, int n_in,
                              void* d_out, int out_size)
{
    (void)in_sizes; (void)n_in; (void)out_size;
    const float* x  = (const float*)d_in[0];
    const float* Wq = (const float*)d_in[2];
    const float* bq = (const float*)d_in[3];
    const float* Wk = (const float*)d_in[4];
    const float* bk = (const float*)d_in[5];
    const float* Wv = (const float*)d_in[6];
    const float* bv = (const float*)d_in[7];
    const float* Wo = (const float*)d_in[8];
    const float* bo = (const float*)d_in[9];
    float* out = (float*)d_out;

    __half *xh, *xl, *wth, *qh, *ql, *kh, *kl, *vth, *vtl, *ph, *pl, *oh, *ol;
    float *v32, *lb;
    cudaGetSymbolAddress((void**)&xh,  g_xh);
    cudaGetSymbolAddress((void**)&xl,  g_xl);
    cudaGetSymbolAddress((void**)&wth, g_wth);
    cudaGetSymbolAddress((void**)&qh,  g_qh);
    cudaGetSymbolAddress((void**)&ql,  g_ql);
    cudaGetSymbolAddress((void**)&kh,  g_kh);
    cudaGetSymbolAddress((void**)&kl,  g_kl);
    cudaGetSymbolAddress((void**)&v32, g_v);
    cudaGetSymbolAddress((void**)&vth, g_vth);
    cudaGetSymbolAddress((void**)&vtl, g_vtl);
    cudaGetSymbolAddress((void**)&ph,  g_ph);
    cudaGetSymbolAddress((void**)&pl,  g_pl);
    cudaGetSymbolAddress((void**)&lb,  g_l);
    cudaGetSymbolAddress((void**)&oh,  g_oh);
    cudaGetSymbolAddress((void**)&ol,  g_ol);

    cudaFuncSetAttribute(gemm_u<2, 0>, cudaFuncAttributeMaxDynamicSharedMemorySize, 3 * 24576);
    cudaFuncSetAttribute(gemm_u<2, 1>, cudaFuncAttributeMaxDynamicSharedMemorySize, 3 * 24576);
    cudaFuncSetAttribute(gemm_u<3, 2>, cudaFuncAttributeMaxDynamicSharedMemorySize, 3 * 32768);
    cudaFuncSetAttribute(gemm_u<3, 3>, cudaFuncAttributeMaxDynamicSharedMemorySize, 3 * 32768);

    const long long sSD = (long long)NS * ND;
    const long long sSS = (long long)NS * NS;
    const long long WSZ = (long long)ND * ND;

    // launch 0: split x
    split_k<<<32768, 256>>>(x, xh, xl, (long long)TOK * ND);
    // launch 1: transpose weights (hi only)
    {
        dim3 g(ND / 32, ND / 32, 4), b(32, 8, 1);
        tsplit_w4<<<g, b>>>(Wq, Wk, Wv, Wo, wth);
    }
    // launch 2: zero row-sum buffer
    zero_l<<<(NB * NH * NS) / 1024, 256>>>(lb);

    // launches 3-5: Q/K/V projections (2-product)
    const dim3 gproj(ND / 128, TOK / 128, 1);
    gemm_u<2, 1><<<gproj, 256, 3 * 24576>>>(xh, xl, wth + 0 * WSZ, nullptr,
        bq, nullptr, 1.0f, nullptr, qh, ql,
        ND, ND, ND, ND, 1, 0, 0, 0, 0, 0, 0, 0);
    gemm_u<2, 1><<<gproj, 256, 3 * 24576>>>(xh, xl, wth + 1 * WSZ, nullptr,
        bk, nullptr, 1.0f, nullptr, kh, kl,
        ND, ND, ND, ND, 1, 0, 0, 0, 0, 0, 0, 0);
    gemm_u<2, 0><<<gproj, 256, 3 * 24576>>>(xh, xl, wth + 2 * WSZ, nullptr,
        bv, nullptr, 1.0f, v32, nullptr, nullptr,
        ND, ND, ND, ND, 1, 0, 0, 0, 0, 0, 0, 0);

    // launch 6: transpose+split V per batch: [S,D] -> [D,S]
    {
        dim3 g(ND / 32, NS / 32, NB), b(32, 8, 1);
        tsplit_k<<<g, b>>>(v32, vth, vtl, NS, ND, sSD, sSD);
    }

    // launch 7: QK -> P = exp(scale*QK^T) split fp16 + row sums (3-product)
    {
        dim3 g(NS / 128, NS / 128, NB * NH);
        gemm_u<3, 2><<<g, 256, 3 * 32768>>>(qh, ql, kh, kl,
            nullptr, lb, ATT_SCALE, nullptr, ph, pl,
            HD, ND, ND, NS, NH, sSD, HD, sSD, HD,
            (long long)NH * sSS, sSS, NS);
    }

    // launch 8: O = (P/l) V  (plain pipelined GEMM, 3-product, row-scaled)
    {
        dim3 g(1, NS / 128, NB * NH);
        gemm_u<3, 3><<<g, 256, 3 * 32768>>>(ph, pl, vth, vtl,
            nullptr, lb, 1.0f, nullptr, oh, ol,
            NS, NS, NS, ND, NH, (long long)NH * sSS, sSS,
            sSD, (long long)HD * NS, sSD, HD, NS);
    }

    // launch 9: final projection -> d_out (2-product)
    gemm_u<2, 0><<<gproj, 256, 3 * 24576>>>(oh, ol, wth + 3 * WSZ, nullptr,
        bo, nullptr, 1.0f, out, nullptr, nullptr,
        ND, ND, ND, ND, 1, 0, 0, 0, 0, 0, 0, 0);
}

// round 15
// speedup vs baseline: 1.9497x; 1.1373x over previous
#include <cuda_runtime.h>
#include <cuda_fp16.h>
#include <cstdint>

// Problem constants
#define NB 4
#define NS 2048
#define ND 2048
#define NH 16
#define HD 128
#define ATT_SCALE 0.08838834764831845f

// ---------------------------------------------------------------------------
// Scratch (device globals; allocation inside kernel_launch is forbidden)
// ---------------------------------------------------------------------------
#define TOK (NB * NS)                 // 8192 tokens
__device__ __align__(16) __half g_xh[TOK * ND];
__device__ __align__(16) __half g_xl[TOK * ND];
__device__ __align__(16) __half g_wth[4][ND * ND];          // W^T hi only
__device__ __align__(16) __half g_qh[TOK * ND];
__device__ __align__(16) __half g_ql[TOK * ND];
__device__ __align__(16) __half g_kh[TOK * ND];
__device__ __align__(16) __half g_kl[TOK * ND];
__device__ __align__(16) float  g_v [TOK * ND];
__device__ __align__(16) __half g_vth[TOK * ND];            // V^T per batch [D][S]
__device__ __align__(16) __half g_vtl[TOK * ND];
__device__ __align__(16) __half g_ph[(long long)NB * NH * NS * NS]; // 512 MB
__device__ __align__(16) float  g_l [NB * NH * NS];         // row sums of exp
__device__ __align__(16) __half g_oh[TOK * ND];
__device__ __align__(16) __half g_ol[TOK * ND];

// ---------------------------------------------------------------------------
// helpers
// ---------------------------------------------------------------------------
__device__ __forceinline__ uint32_t smem_u32(const void* p) {
    uint32_t a;
    asm("{ .reg .u64 t; cvta.to.shared.u64 t, %1; cvt.u32.u64 %0, t; }"
        : "=r"(a) : "l"(p));
    return a;
}
__device__ __forceinline__ void cpa16(uint32_t dst, const void* src) {
    asm volatile("cp.async.cg.shared.global [%0], [%1], 16;"
                 :: "r"(dst), "l"(src) : "memory");
}
#define CP_COMMIT() asm volatile("cp.async.commit_group;" ::: "memory")
#define CP_WAIT0()  asm volatile("cp.async.wait_group 0;" ::: "memory")
#define CP_WAIT1()  asm volatile("cp.async.wait_group 1;" ::: "memory")

__device__ __forceinline__ void ldsm4(uint32_t* r, uint32_t addr) {
    asm volatile("ldmatrix.sync.aligned.m8n8.x4.shared.b16 {%0,%1,%2,%3}, [%4];"
                 : "=r"(r[0]), "=r"(r[1]), "=r"(r[2]), "=r"(r[3]) : "r"(addr));
}
__device__ __forceinline__ void mma16816(float* d, const uint32_t* a,
                                         const uint32_t* b) {
    asm volatile(
        "mma.sync.aligned.m16n8k16.row.col.f32.f16.f16.f32 "
        "{%0,%1,%2,%3}, {%4,%5,%6,%7}, {%8,%9}, {%0,%1,%2,%3};"
        : "+f"(d[0]), "+f"(d[1]), "+f"(d[2]), "+f"(d[3])
        : "r"(a[0]), "r"(a[1]), "r"(a[2]), "r"(a[3]), "r"(b[0]), "r"(b[1]));
}
__device__ __forceinline__ void split2h(float v, __half& h, __half& l) {
    h = __float2half(v);
    l = __float2half(v - __half2float(h));
}
// pack (e0,e1) -> f16x2 hi pair + lo (residual) pair; low half = e0
__device__ __forceinline__ void split_pair(float e0, float e1,
                                           uint32_t& hp, uint32_t& lp) {
    asm("cvt.rn.f16x2.f32 %0, %1, %2;" : "=r"(hp) : "f"(e1), "f"(e0));
    __half2 hb = *reinterpret_cast<__half2*>(&hp);
    const float l0 = e0 - __half2float(hb.x);
    const float l1 = e1 - __half2float(hb.y);
    asm("cvt.rn.f16x2.f32 %0, %1, %2;" : "=r"(lp) : "f"(l1), "f"(l0));
}
__device__ __forceinline__ uint32_t pack_pair(float e0, float e1) {
    uint32_t hp;
    asm("cvt.rn.f16x2.f32 %0, %1, %2;" : "=r"(hp) : "f"(e1), "f"(e0));
    return hp;
}

// ---------------------------------------------------------------------------
// gemm_u: unified 2-CTA/SM tensor-core GEMM, 256 threads, tile 128x128,
// K-chunk 32, 3 smem stages, cp.async 2-deep prefetch, 64B-row swizzle.
// C[M,N] = A[M,K] * B[N,K]^T.
// AP=2: A = Ah+Al split (adds AlBh product). AP=1: A = Ah only.
// BP=2: B = Bh+Bl split (adds AhBl product). BP=1: B = Bh only.
// OMODE 0: Cf = alpha*acc + bias (fp32)
// OMODE 1: split fp16 out = alpha*acc + bias
// OMODE 2: Ch = exp(alpha*acc) fp16 (hi only) + atomic row-sums into lbuf
// OMODE 3: split fp16 out = acc / lbuf[row]
// stage: Ah@0 [Al@8192] Bh@(AP*8K) [Bl@(AP*8K+8K)]; stage size (AP+BP)*8KB
// ---------------------------------------------------------------------------
template <int AP, int BP, int OMODE>
__global__ void __launch_bounds__(256, 2) gemm_u(
    const __half* __restrict__ Ah, const __half* __restrict__ Al,
    const __half* __restrict__ Bh, const __half* __restrict__ Bl,
    const float* __restrict__ bias, float* __restrict__ lbuf,
    float alpha,
    float* __restrict__ Cf, __half* __restrict__ Ch, __half* __restrict__ Cl,
    int K, int lda, int ldb, int ldc, int hdiv,
    long long sa1, long long sa2, long long sb1, long long sb2,
    long long sc1, long long sc2, int lstride)
{
    constexpr uint32_t BOFF  = AP * 8192u;
    constexpr uint32_t STAGE = (AP + BP) * 8192u;
    extern __shared__ char smem[];
    const int tid = threadIdx.x;
    const uint32_t sb32 = smem_u32(smem);

    const int bz = blockIdx.z;
    const int zb = bz / hdiv;
    const int zh = bz - zb * hdiv;
    Ah += zb * sa1 + zh * sa2;
    if (AP == 2) Al += zb * sa1 + zh * sa2;
    Bh += zb * sb1 + zh * sb2;
    if (BP == 2) Bl += zb * sb1 + zh * sb2;
    const long long coff = zb * sc1 + zh * sc2;
    const long long loff = (long long)bz * lstride;

    const int m0 = blockIdx.y * 128;
    const int n0 = blockIdx.x * 128;

    // loader geometry: 512 16B-chunks per 8KB matrix-tile, 2 per thread
    long long aoff[2], boff[2];
    uint32_t ssw[2];
    #pragma unroll
    for (int q = 0; q < 2; ++q) {
        const int idx = tid + q * 256;
        const int row = idx >> 2;
        const int c16 = idx & 3;
        aoff[q] = (long long)(m0 + row) * lda + c16 * 8;
        boff[q] = (long long)(n0 + row) * ldb + c16 * 8;
        const uint32_t bo = row * 64 + c16 * 16;
        ssw[q] = bo ^ ((bo >> 3) & 0x30);
    }

    // warp compute geometry: 8 warps = 2(m) x 4(n); warp tile 64x32
    const int lane = tid & 31, warp = tid >> 5;
    const int wm = warp >> 2;
    const int wn = warp & 3;
    const int sx = lane & 7;
    const int am8 = (lane >> 3) & 1;
    const int ach = (lane >> 4) & 1;
    const int bn8 = (lane >> 4) & 1;
    const int bch = (lane >> 3) & 1;
    const uint32_t askewA = (uint32_t)((sx >> 1) & 3);
    uint32_t aro[4], bro[2];
    #pragma unroll
    for (int i = 0; i < 4; ++i)
        aro[i] = (uint32_t)(wm * 64 + i * 16 + sx + am8 * 8) * 64;
    #pragma unroll
    for (int j2 = 0; j2 < 2; ++j2)
        bro[j2] = (uint32_t)(wn * 32 + j2 * 16 + sx + bn8 * 8) * 64;

    float acc[4][4][4];
    #pragma unroll
    for (int i = 0; i < 4; ++i)
        #pragma unroll
        for (int j = 0; j < 4; ++j)
            #pragma unroll
            for (int e = 0; e < 4; ++e) acc[i][j][e] = 0.0f;

    const int nT = K >> 5;

    // prologue: issue stages 0 and 1
    #pragma unroll
    for (int s = 0; s < 2; ++s) {
        if (s < nT) {
            const uint32_t db = sb32 + s * STAGE;
            const int kb = s << 5;
            #pragma unroll
            for (int q = 0; q < 2; ++q) {
                cpa16(db + ssw[q], Ah + aoff[q] + kb);
                if (AP == 2)
                    cpa16(db + 8192 + ssw[q], Al + aoff[q] + kb);
                cpa16(db + BOFF + ssw[q], Bh + boff[q] + kb);
                if (BP == 2)
                    cpa16(db + BOFF + 8192 + ssw[q], Bl + boff[q] + kb);
            }
            CP_COMMIT();
        }
    }

    int stage = 0;
    for (int t = 0; t < nT; ++t) {
        if (t + 1 < nT) CP_WAIT1(); else CP_WAIT0();
        __syncthreads();

        if (t + 2 < nT) {
            const uint32_t db = sb32 + ((stage + 2) % 3) * STAGE;
            const int kb = (t + 2) << 5;
            #pragma unroll
            for (int q = 0; q < 2; ++q) {
                cpa16(db + ssw[q], Ah + aoff[q] + kb);
                if (AP == 2)
                    cpa16(db + 8192 + ssw[q], Al + aoff[q] + kb);
                cpa16(db + BOFF + ssw[q], Bh + boff[q] + kb);
                if (BP == 2)
                    cpa16(db + BOFF + 8192 + ssw[q], Bl + boff[q] + kb);
            }
            CP_COMMIT();
        }

        const uint32_t Abase = sb32 + stage * STAGE;
        const uint32_t Bbase = Abase + BOFF;
        #pragma unroll
        for (int ks = 0; ks < 2; ++ks) {
            uint32_t ah[4][4], alr[4][4], bh[4][2], bl[4][2];
            const uint32_t kxa = ((uint32_t)(((ks << 1) | ach)) ^ askewA) << 4;
            const uint32_t kxb = ((uint32_t)(((ks << 1) | bch)) ^ askewA) << 4;
            #pragma unroll
            for (int i = 0; i < 4; ++i) {
                ldsm4(ah[i], Abase + aro[i] + kxa);
                if (AP == 2)
                    ldsm4(alr[i], Abase + 8192 + aro[i] + kxa);
            }
            #pragma unroll
            for (int j2 = 0; j2 < 2; ++j2) {
                uint32_t r[4];
                ldsm4(r, Bbase + bro[j2] + kxb);
                bh[j2 * 2][0] = r[0];  bh[j2 * 2][1] = r[1];
                bh[j2 * 2 + 1][0] = r[2];  bh[j2 * 2 + 1][1] = r[3];
                if (BP == 2) {
                    uint32_t r2[4];
                    ldsm4(r2, Bbase + 8192 + bro[j2] + kxb);
                    bl[j2 * 2][0] = r2[0]; bl[j2 * 2][1] = r2[1];
                    bl[j2 * 2 + 1][0] = r2[2]; bl[j2 * 2 + 1][1] = r2[3];
                }
            }
            #pragma unroll
            for (int i = 0; i < 4; ++i)
                #pragma unroll
                for (int j = 0; j < 4; ++j) {
                    mma16816(acc[i][j], ah[i], bh[j]);
                    if (AP == 2)
                        mma16816(acc[i][j], alr[i], bh[j]);
                    if (BP == 2)
                        mma16816(acc[i][j], ah[i], bl[j]);
                }
        }
        stage = (stage + 1) % 3;
    }

    // ---- epilogue ----
    const int erow = m0 + wm * 64 + (lane >> 2);
    const int ecol = n0 + wn * 32 + (lane & 3) * 2;

    if (OMODE == 2) {
        // P = exp(alpha*acc) fp16 (hi only) + atomic row sums
        float rsum[4][2];
        #pragma unroll
        for (int i = 0; i < 4; ++i) { rsum[i][0] = 0.0f; rsum[i][1] = 0.0f; }
        #pragma unroll
        for (int j = 0; j < 4; ++j) {
            const int c = ecol + j * 8;
            #pragma unroll
            for (int i = 0; i < 4; ++i) {
                const float e0 = __expf(acc[i][j][0] * alpha);
                const float e1 = __expf(acc[i][j][1] * alpha);
                const float e2 = __expf(acc[i][j][2] * alpha);
                const float e3 = __expf(acc[i][j][3] * alpha);
                rsum[i][0] += e0 + e1;
                rsum[i][1] += e2 + e3;
                const long long o0 = coff + (long long)(erow + i * 16) * ldc + c;
                const long long o1 = o0 + 8ll * ldc;
                *(uint32_t*)(Ch + o0) = pack_pair(e0, e1);
                *(uint32_t*)(Ch + o1) = pack_pair(e2, e3);
            }
        }
        #pragma unroll
        for (int i = 0; i < 4; ++i)
            #pragma unroll
            for (int par = 0; par < 2; ++par) {
                float v = rsum[i][par];
                v += __shfl_xor_sync(0xffffffffu, v, 1);
                v += __shfl_xor_sync(0xffffffffu, v, 2);
                if ((lane & 3) == 0)
                    atomicAdd(lbuf + loff + erow + i * 16 + par * 8, v);
            }
        return;
    }

    #pragma unroll
    for (int j = 0; j < 4; ++j) {
        const int c = ecol + j * 8;
        float b0 = 0.0f, b1 = 0.0f;
        if (OMODE == 0 || OMODE == 1) {
            b0 = bias ? __ldg(bias + c)     : 0.0f;
            b1 = bias ? __ldg(bias + c + 1) : 0.0f;
        }
        #pragma unroll
        for (int i = 0; i < 4; ++i) {
            float s0 = alpha, s1 = alpha;
            if (OMODE == 3) {
                s0 = 1.0f / __ldg(lbuf + loff + erow + i * 16);
                s1 = 1.0f / __ldg(lbuf + loff + erow + i * 16 + 8);
            }
            const float v0 = acc[i][j][0] * s0 + b0;
            const float v1 = acc[i][j][1] * s0 + b1;
            const float v2 = acc[i][j][2] * s1 + b0;
            const float v3 = acc[i][j][3] * s1 + b1;
            const long long o0 = coff + (long long)(erow + i * 16) * ldc + c;
            const long long o1 = o0 + 8ll * ldc;
            if (OMODE == 0) {
                *(float2*)(Cf + o0) = make_float2(v0, v1);
                *(float2*)(Cf + o1) = make_float2(v2, v3);
            } else {
                uint32_t hp, lp;
                split_pair(v0, v1, hp, lp);
                *(uint32_t*)(Ch + o0) = hp;
                *(uint32_t*)(Cl + o0) = lp;
                split_pair(v2, v3, hp, lp);
                *(uint32_t*)(Ch + o1) = hp;
                *(uint32_t*)(Cl + o1) = lp;
            }
        }
    }
}

// ---------------------------------------------------------------------------
// fp32 -> split fp16 (elementwise)
// ---------------------------------------------------------------------------
__global__ void __launch_bounds__(256) split_k(const float* __restrict__ in,
                                               __half* __restrict__ oh,
                                               __half* __restrict__ ol,
                                               long long n)
{
    for (long long i = blockIdx.x * 256ll + threadIdx.x; i < n;
         i += (long long)gridDim.x * 256) {
        __half h, l;
        split2h(in[i], h, l);
        oh[i] = h; ol[i] = l;
    }
}

// ---------------------------------------------------------------------------
// transpose + split fp16 hi/lo (z-batched)
// ---------------------------------------------------------------------------
__global__ void __launch_bounds__(256) tsplit_k(const float* __restrict__ in,
                                                __half* __restrict__ oh,
                                                __half* __restrict__ ol,
                                                int R, int C,
                                                long long inB, long long outB)
{
    __shared__ float t[32][33];
    const int b = blockIdx.z;
    in += b * inB; oh += b * outB; ol += b * outB;
    const int x = blockIdx.x * 32 + threadIdx.x;
    const int y0 = blockIdx.y * 32;
    #pragma unroll
    for (int i = 0; i < 4; ++i)
        t[threadIdx.y + i * 8][threadIdx.x] =
            in[(long long)(y0 + threadIdx.y + i * 8) * C + x];
    __syncthreads();
    const int ox = y0 + threadIdx.x;
    const int oy = blockIdx.x * 32;
    #pragma unroll
    for (int i = 0; i < 4; ++i) {
        const float v = t[threadIdx.x][threadIdx.y + i * 8];
        __half h, l;
        split2h(v, h, l);
        const long long o = (long long)(oy + threadIdx.y + i * 8) * R + ox;
        oh[o] = h; ol[o] = l;
    }
}

// transpose all 4 weight matrices, hi only (2-product B operand)
__global__ void __launch_bounds__(256) tsplit_w4(
    const float* __restrict__ in0, const float* __restrict__ in1,
    const float* __restrict__ in2, const float* __restrict__ in3,
    __half* __restrict__ oh)
{
    __shared__ float t[32][33];
    const int b = blockIdx.z;
    const float* in = (b == 0) ? in0 : (b == 1) ? in1 : (b == 2) ? in2 : in3;
    oh += (long long)b * ND * ND;
    const int x = blockIdx.x * 32 + threadIdx.x;
    const int y0 = blockIdx.y * 32;
    #pragma unroll
    for (int i = 0; i < 4; ++i)
        t[threadIdx.y + i * 8][threadIdx.x] =
            in[(long long)(y0 + threadIdx.y + i * 8) * ND + x];
    __syncthreads();
    const int oy = blockIdx.x * 32;
    const int ox = y0 + threadIdx.x;
    #pragma unroll
    for (int i = 0; i < 4; ++i) {
        const float v = t[threadIdx.x][threadIdx.y + i * 8];
        const long long o = (long long)(oy + threadIdx.y + i * 8) * ND + ox;
        oh[o] = __float2half(v);
    }
}

__global__ void __launch_bounds__(256) zero_l(float* __restrict__ l)
{
    const int i = blockIdx.x * 256 + threadIdx.x;
    ((float4*)l)[i] = make_float4(0.f, 0.f, 0.f, 0.f);
}

// ---------------------------------------------------------------------------
extern "C" void kernel_launch(void* const* d_in, const int* in_sizes, int n_in,
                              void* d_out, int out_size)
{
    (void)in_sizes; (void)n_in; (void)out_size;
    const float* x  = (const float*)d_in[0];
    const float* Wq = (const float*)d_in[2];
    const float* bq = (const float*)d_in[3];
    const float* Wk = (const float*)d_in[4];
    const float* bk = (const float*)d_in[5];
    const float* Wv = (const float*)d_in[6];
    const float* bv = (const float*)d_in[7];
    const float* Wo = (const float*)d_in[8];
    const float* bo = (const float*)d_in[9];
    float* out = (float*)d_out;

    __half *xh, *xl, *wth, *qh, *ql, *kh, *kl, *vth, *vtl, *ph, *oh, *ol;
    float *v32, *lb;
    cudaGetSymbolAddress((void**)&xh,  g_xh);
    cudaGetSymbolAddress((void**)&xl,  g_xl);
    cudaGetSymbolAddress((void**)&wth, g_wth);
    cudaGetSymbolAddress((void**)&qh,  g_qh);
    cudaGetSymbolAddress((void**)&ql,  g_ql);
    cudaGetSymbolAddress((void**)&kh,  g_kh);
    cudaGetSymbolAddress((void**)&kl,  g_kl);
    cudaGetSymbolAddress((void**)&v32, g_v);
    cudaGetSymbolAddress((void**)&vth, g_vth);
    cudaGetSymbolAddress((void**)&vtl, g_vtl);
    cudaGetSymbolAddress((void**)&ph,  g_ph);
    cudaGetSymbolAddress((void**)&lb,  g_l);
    cudaGetSymbolAddress((void**)&oh,  g_oh);
    cudaGetSymbolAddress((void**)&ol,  g_ol);

    cudaFuncSetAttribute((const void*)gemm_u<2, 1, 0>,
        cudaFuncAttributeMaxDynamicSharedMemorySize, 3 * 24576);
    cudaFuncSetAttribute((const void*)gemm_u<2, 1, 1>,
        cudaFuncAttributeMaxDynamicSharedMemorySize, 3 * 24576);
    cudaFuncSetAttribute((const void*)gemm_u<2, 2, 2>,
        cudaFuncAttributeMaxDynamicSharedMemorySize, 3 * 32768);
    cudaFuncSetAttribute((const void*)gemm_u<1, 2, 3>,
        cudaFuncAttributeMaxDynamicSharedMemorySize, 3 * 24576);

    const long long sSD = (long long)NS * ND;
    const long long sSS = (long long)NS * NS;
    const long long WSZ = (long long)ND * ND;

    // launch 0: split x
    split_k<<<32768, 256>>>(x, xh, xl, (long long)TOK * ND);
    // launch 1: transpose weights (hi only)
    {
        dim3 g(ND / 32, ND / 32, 4), b(32, 8, 1);
        tsplit_w4<<<g, b>>>(Wq, Wk, Wv, Wo, wth);
    }
    // launch 2: zero row-sum buffer
    zero_l<<<(NB * NH * NS) / 1024, 256>>>(lb);

    // launches 3-5: Q/K/V projections (exact-A x fp16-W, 2 products)
    const dim3 gproj(ND / 128, TOK / 128, 1);
    gemm_u<2, 1, 1><<<gproj, 256, 3 * 24576>>>(xh, xl, wth + 0 * WSZ, nullptr,
        bq, nullptr, 1.0f, nullptr, qh, ql,
        ND, ND, ND, ND, 1, 0, 0, 0, 0, 0, 0, 0);
    gemm_u<2, 1, 1><<<gproj, 256, 3 * 24576>>>(xh, xl, wth + 1 * WSZ, nullptr,
        bk, nullptr, 1.0f, nullptr, kh, kl,
        ND, ND, ND, ND, 1, 0, 0, 0, 0, 0, 0, 0);
    gemm_u<2, 1, 0><<<gproj, 256, 3 * 24576>>>(xh, xl, wth + 2 * WSZ, nullptr,
        bv, nullptr, 1.0f, v32, nullptr, nullptr,
        ND, ND, ND, ND, 1, 0, 0, 0, 0, 0, 0, 0);

    // launch 6: transpose+split V per batch: [S,D] -> [D,S]
    {
        dim3 g(ND / 32, NS / 32, NB), b(32, 8, 1);
        tsplit_k<<<g, b>>>(v32, vth, vtl, NS, ND, sSD, sSD);
    }

    // launch 7: QK -> P = exp(scale*QK^T) fp16 hi + row sums (3 products)
    {
        dim3 g(NS / 128, NS / 128, NB * NH);
        gemm_u<2, 2, 2><<<g, 256, 3 * 32768>>>(qh, ql, kh, kl,
            nullptr, lb, ATT_SCALE, nullptr, ph, nullptr,
            HD, ND, ND, NS, NH, sSD, HD, sSD, HD,
            (long long)NH * sSS, sSS, NS);
    }

    // launch 8: O = (P/l) V  (fp16-P x exact-V, 2 products, row-scaled)
    {
        dim3 g(1, NS / 128, NB * NH);
        gemm_u<1, 2, 3><<<g, 256, 3 * 24576>>>(ph, nullptr, vth, vtl,
            nullptr, lb, 1.0f, nullptr, oh, ol,
            NS, NS, NS, ND, NH, (long long)NH * sSS, sSS,
            sSD, (long long)HD * NS, sSD, HD, NS);
    }

    // launch 9: final projection -> d_out (exact-O x fp16-W, 2 products)
    gemm_u<2, 1, 0><<<gproj, 256, 3 * 24576>>>(oh, ol, wth + 3 * WSZ, nullptr,
        bo, nullptr, 1.0f, out, nullptr, nullptr,
        ND, ND, ND, ND, 1, 0, 0, 0, 0, 0, 0, 0);
}

// round 16
// speedup vs baseline: 2.0288x; 1.0405x over previous
#include <cuda_runtime.h>
#include <cuda_fp16.h>
#include <cstdint>

// Problem constants
#define NB 4
#define NS 2048
#define ND 2048
#define NH 16
#define HD 128
#define ATT_SCALE 0.08838834764831845f

// ---------------------------------------------------------------------------
// Scratch (device globals; allocation inside kernel_launch is forbidden)
// ---------------------------------------------------------------------------
#define TOK (NB * NS)                 // 8192 tokens
__device__ __align__(16) __half g_xh[TOK * ND];
__device__ __align__(16) __half g_xl[TOK * ND];
__device__ __align__(16) __half g_wth[4][ND * ND];          // W^T hi only
__device__ __align__(16) __half g_qh[TOK * ND];
__device__ __align__(16) __half g_ql[TOK * ND];
__device__ __align__(16) __half g_kh[TOK * ND];             // K hi only
__device__ __align__(16) float  g_v [TOK * ND];
__device__ __align__(16) __half g_vth[TOK * ND];            // V^T per batch [D][S]
__device__ __align__(16) __half g_vtl[TOK * ND];
__device__ __align__(16) __half g_ph[(long long)NB * NH * NS * NS]; // 512 MB
__device__ __align__(16) float  g_l [NB * NH * NS];         // row sums of exp
__device__ __align__(16) __half g_oh[TOK * ND];
__device__ __align__(16) __half g_ol[TOK * ND];

// ---------------------------------------------------------------------------
// helpers
// ---------------------------------------------------------------------------
__device__ __forceinline__ uint32_t smem_u32(const void* p) {
    uint32_t a;
    asm("{ .reg .u64 t; cvta.to.shared.u64 t, %1; cvt.u32.u64 %0, t; }"
        : "=r"(a) : "l"(p));
    return a;
}
__device__ __forceinline__ void cpa16(uint32_t dst, const void* src) {
    asm volatile("cp.async.cg.shared.global [%0], [%1], 16;"
                 :: "r"(dst), "l"(src) : "memory");
}
#define CP_COMMIT() asm volatile("cp.async.commit_group;" ::: "memory")
#define CP_WAIT0()  asm volatile("cp.async.wait_group 0;" ::: "memory")
#define CP_WAIT1()  asm volatile("cp.async.wait_group 1;" ::: "memory")

__device__ __forceinline__ void ldsm4(uint32_t* r, uint32_t addr) {
    asm volatile("ldmatrix.sync.aligned.m8n8.x4.shared.b16 {%0,%1,%2,%3}, [%4];"
                 : "=r"(r[0]), "=r"(r[1]), "=r"(r[2]), "=r"(r[3]) : "r"(addr));
}
__device__ __forceinline__ void mma16816(float* d, const uint32_t* a,
                                         const uint32_t* b) {
    asm volatile(
        "mma.sync.aligned.m16n8k16.row.col.f32.f16.f16.f32 "
        "{%0,%1,%2,%3}, {%4,%5,%6,%7}, {%8,%9}, {%0,%1,%2,%3};"
        : "+f"(d[0]), "+f"(d[1]), "+f"(d[2]), "+f"(d[3])
        : "r"(a[0]), "r"(a[1]), "r"(a[2]), "r"(a[3]), "r"(b[0]), "r"(b[1]));
}
__device__ __forceinline__ void split2h(float v, __half& h, __half& l) {
    h = __float2half(v);
    l = __float2half(v - __half2float(h));
}
// pack (e0,e1) -> f16x2 hi pair + lo (residual) pair; low half = e0
__device__ __forceinline__ void split_pair(float e0, float e1,
                                           uint32_t& hp, uint32_t& lp) {
    asm("cvt.rn.f16x2.f32 %0, %1, %2;" : "=r"(hp) : "f"(e1), "f"(e0));
    __half2 hb = *reinterpret_cast<__half2*>(&hp);
    const float l0 = e0 - __half2float(hb.x);
    const float l1 = e1 - __half2float(hb.y);
    asm("cvt.rn.f16x2.f32 %0, %1, %2;" : "=r"(lp) : "f"(l1), "f"(l0));
}
__device__ __forceinline__ uint32_t pack_pair(float e0, float e1) {
    uint32_t hp;
    asm("cvt.rn.f16x2.f32 %0, %1, %2;" : "=r"(hp) : "f"(e1), "f"(e0));
    return hp;
}

// ---------------------------------------------------------------------------
// gemm_u: unified 2-CTA/SM tensor-core GEMM, 256 threads, tile 128x128,
// K-chunk 32, 3 smem stages, cp.async 2-deep prefetch, 64B-row swizzle.
// C[M,N] = A[M,K] * B[N,K]^T.
// AP=2: A = Ah+Al split (adds AlBh product). AP=1: A = Ah only.
// BP=2: B = Bh+Bl split (adds AhBl product). BP=1: B = Bh only.
// OMODE 0: Cf = alpha*acc + bias (fp32)
// OMODE 1: split fp16 out = alpha*acc + bias
// OMODE 2: Ch = exp(alpha*acc) fp16 (hi only) + atomic row-sums into lbuf
// OMODE 3: split fp16 out = acc / lbuf[row]
// OMODE 4: Ch = alpha*acc + bias, fp16 hi only
// stage: Ah@0 [Al@8192] Bh@(AP*8K) [Bl@(AP*8K+8K)]; stage size (AP+BP)*8KB
// ---------------------------------------------------------------------------
template <int AP, int BP, int OMODE>
__global__ void __launch_bounds__(256, 2) gemm_u(
    const __half* __restrict__ Ah, const __half* __restrict__ Al,
    const __half* __restrict__ Bh, const __half* __restrict__ Bl,
    const float* __restrict__ bias, float* __restrict__ lbuf,
    float alpha,
    float* __restrict__ Cf, __half* __restrict__ Ch, __half* __restrict__ Cl,
    int K, int lda, int ldb, int ldc, int hdiv,
    long long sa1, long long sa2, long long sb1, long long sb2,
    long long sc1, long long sc2, int lstride)
{
    constexpr uint32_t BOFF  = AP * 8192u;
    constexpr uint32_t STAGE = (AP + BP) * 8192u;
    extern __shared__ char smem[];
    const int tid = threadIdx.x;
    const uint32_t sb32 = smem_u32(smem);

    const int bz = blockIdx.z;
    const int zb = bz / hdiv;
    const int zh = bz - zb * hdiv;
    Ah += zb * sa1 + zh * sa2;
    if (AP == 2) Al += zb * sa1 + zh * sa2;
    Bh += zb * sb1 + zh * sb2;
    if (BP == 2) Bl += zb * sb1 + zh * sb2;
    const long long coff = zb * sc1 + zh * sc2;
    const long long loff = (long long)bz * lstride;

    const int m0 = blockIdx.y * 128;
    const int n0 = blockIdx.x * 128;

    // loader geometry: 512 16B-chunks per 8KB matrix-tile, 2 per thread
    long long aoff[2], boff[2];
    uint32_t ssw[2];
    #pragma unroll
    for (int q = 0; q < 2; ++q) {
        const int idx = tid + q * 256;
        const int row = idx >> 2;
        const int c16 = idx & 3;
        aoff[q] = (long long)(m0 + row) * lda + c16 * 8;
        boff[q] = (long long)(n0 + row) * ldb + c16 * 8;
        const uint32_t bo = row * 64 + c16 * 16;
        ssw[q] = bo ^ ((bo >> 3) & 0x30);
    }

    // warp compute geometry: 8 warps = 2(m) x 4(n); warp tile 64x32
    const int lane = tid & 31, warp = tid >> 5;
    const int wm = warp >> 2;
    const int wn = warp & 3;
    const int sx = lane & 7;
    const int am8 = (lane >> 3) & 1;
    const int ach = (lane >> 4) & 1;
    const int bn8 = (lane >> 4) & 1;
    const int bch = (lane >> 3) & 1;
    const uint32_t askewA = (uint32_t)((sx >> 1) & 3);
    uint32_t aro[4], bro[2];
    #pragma unroll
    for (int i = 0; i < 4; ++i)
        aro[i] = (uint32_t)(wm * 64 + i * 16 + sx + am8 * 8) * 64;
    #pragma unroll
    for (int j2 = 0; j2 < 2; ++j2)
        bro[j2] = (uint32_t)(wn * 32 + j2 * 16 + sx + bn8 * 8) * 64;

    float acc[4][4][4];
    #pragma unroll
    for (int i = 0; i < 4; ++i)
        #pragma unroll
        for (int j = 0; j < 4; ++j)
            #pragma unroll
            for (int e = 0; e < 4; ++e) acc[i][j][e] = 0.0f;

    const int nT = K >> 5;

    // prologue: issue stages 0 and 1
    #pragma unroll
    for (int s = 0; s < 2; ++s) {
        if (s < nT) {
            const uint32_t db = sb32 + s * STAGE;
            const int kb = s << 5;
            #pragma unroll
            for (int q = 0; q < 2; ++q) {
                cpa16(db + ssw[q], Ah + aoff[q] + kb);
                if (AP == 2)
                    cpa16(db + 8192 + ssw[q], Al + aoff[q] + kb);
                cpa16(db + BOFF + ssw[q], Bh + boff[q] + kb);
                if (BP == 2)
                    cpa16(db + BOFF + 8192 + ssw[q], Bl + boff[q] + kb);
            }
            CP_COMMIT();
        }
    }

    int stage = 0;
    for (int t = 0; t < nT; ++t) {
        if (t + 1 < nT) CP_WAIT1(); else CP_WAIT0();
        __syncthreads();

        if (t + 2 < nT) {
            const uint32_t db = sb32 + ((stage + 2) % 3) * STAGE;
            const int kb = (t + 2) << 5;
            #pragma unroll
            for (int q = 0; q < 2; ++q) {
                cpa16(db + ssw[q], Ah + aoff[q] + kb);
                if (AP == 2)
                    cpa16(db + 8192 + ssw[q], Al + aoff[q] + kb);
                cpa16(db + BOFF + ssw[q], Bh + boff[q] + kb);
                if (BP == 2)
                    cpa16(db + BOFF + 8192 + ssw[q], Bl + boff[q] + kb);
            }
            CP_COMMIT();
        }

        const uint32_t Abase = sb32 + stage * STAGE;
        const uint32_t Bbase = Abase + BOFF;
        #pragma unroll
        for (int ks = 0; ks < 2; ++ks) {
            uint32_t ah[4][4], alr[4][4], bh[4][2], bl[4][2];
            const uint32_t kxa = ((uint32_t)(((ks << 1) | ach)) ^ askewA) << 4;
            const uint32_t kxb = ((uint32_t)(((ks << 1) | bch)) ^ askewA) << 4;
            #pragma unroll
            for (int i = 0; i < 4; ++i) {
                ldsm4(ah[i], Abase + aro[i] + kxa);
                if (AP == 2)
                    ldsm4(alr[i], Abase + 8192 + aro[i] + kxa);
            }
            #pragma unroll
            for (int j2 = 0; j2 < 2; ++j2) {
                uint32_t r[4];
                ldsm4(r, Bbase + bro[j2] + kxb);
                bh[j2 * 2][0] = r[0];  bh[j2 * 2][1] = r[1];
                bh[j2 * 2 + 1][0] = r[2];  bh[j2 * 2 + 1][1] = r[3];
                if (BP == 2) {
                    uint32_t r2[4];
                    ldsm4(r2, Bbase + 8192 + bro[j2] + kxb);
                    bl[j2 * 2][0] = r2[0]; bl[j2 * 2][1] = r2[1];
                    bl[j2 * 2 + 1][0] = r2[2]; bl[j2 * 2 + 1][1] = r2[3];
                }
            }
            #pragma unroll
            for (int i = 0; i < 4; ++i)
                #pragma unroll
                for (int j = 0; j < 4; ++j) {
                    mma16816(acc[i][j], ah[i], bh[j]);
                    if (AP == 2)
                        mma16816(acc[i][j], alr[i], bh[j]);
                    if (BP == 2)
                        mma16816(acc[i][j], ah[i], bl[j]);
                }
        }
        stage = (stage + 1) % 3;
    }

    // ---- epilogue ----
    const int erow = m0 + wm * 64 + (lane >> 2);
    const int ecol = n0 + wn * 32 + (lane & 3) * 2;

    if (OMODE == 2) {
        // P = exp(alpha*acc) fp16 (hi only) + atomic row sums
        float rsum[4][2];
        #pragma unroll
        for (int i = 0; i < 4; ++i) { rsum[i][0] = 0.0f; rsum[i][1] = 0.0f; }
        #pragma unroll
        for (int j = 0; j < 4; ++j) {
            const int c = ecol + j * 8;
            #pragma unroll
            for (int i = 0; i < 4; ++i) {
                const float e0 = __expf(acc[i][j][0] * alpha);
                const float e1 = __expf(acc[i][j][1] * alpha);
                const float e2 = __expf(acc[i][j][2] * alpha);
                const float e3 = __expf(acc[i][j][3] * alpha);
                rsum[i][0] += e0 + e1;
                rsum[i][1] += e2 + e3;
                const long long o0 = coff + (long long)(erow + i * 16) * ldc + c;
                const long long o1 = o0 + 8ll * ldc;
                *(uint32_t*)(Ch + o0) = pack_pair(e0, e1);
                *(uint32_t*)(Ch + o1) = pack_pair(e2, e3);
            }
        }
        #pragma unroll
        for (int i = 0; i < 4; ++i)
            #pragma unroll
            for (int par = 0; par < 2; ++par) {
                float v = rsum[i][par];
                v += __shfl_xor_sync(0xffffffffu, v, 1);
                v += __shfl_xor_sync(0xffffffffu, v, 2);
                if ((lane & 3) == 0)
                    atomicAdd(lbuf + loff + erow + i * 16 + par * 8, v);
            }
        return;
    }

    #pragma unroll
    for (int j = 0; j < 4; ++j) {
        const int c = ecol + j * 8;
        float b0 = 0.0f, b1 = 0.0f;
        if (OMODE == 0 || OMODE == 1 || OMODE == 4) {
            b0 = bias ? __ldg(bias + c)     : 0.0f;
            b1 = bias ? __ldg(bias + c + 1) : 0.0f;
        }
        #pragma unroll
        for (int i = 0; i < 4; ++i) {
            float s0 = alpha, s1 = alpha;
            if (OMODE == 3) {
                s0 = 1.0f / __ldg(lbuf + loff + erow + i * 16);
                s1 = 1.0f / __ldg(lbuf + loff + erow + i * 16 + 8);
            }
            const float v0 = acc[i][j][0] * s0 + b0;
            const float v1 = acc[i][j][1] * s0 + b1;
            const float v2 = acc[i][j][2] * s1 + b0;
            const float v3 = acc[i][j][3] * s1 + b1;
            const long long o0 = coff + (long long)(erow + i * 16) * ldc + c;
            const long long o1 = o0 + 8ll * ldc;
            if (OMODE == 0) {
                *(float2*)(Cf + o0) = make_float2(v0, v1);
                *(float2*)(Cf + o1) = make_float2(v2, v3);
            } else if (OMODE == 4) {
                *(uint32_t*)(Ch + o0) = pack_pair(v0, v1);
                *(uint32_t*)(Ch + o1) = pack_pair(v2, v3);
            } else {
                uint32_t hp, lp;
                split_pair(v0, v1, hp, lp);
                *(uint32_t*)(Ch + o0) = hp;
                *(uint32_t*)(Cl + o0) = lp;
                split_pair(v2, v3, hp, lp);
                *(uint32_t*)(Ch + o1) = hp;
                *(uint32_t*)(Cl + o1) = lp;
            }
        }
    }
}

// ---------------------------------------------------------------------------
// fp32 -> split fp16 (elementwise)
// ---------------------------------------------------------------------------
__global__ void __launch_bounds__(256) split_k(const float* __restrict__ in,
                                               __half* __restrict__ oh,
                                               __half* __restrict__ ol,
                                               long long n)
{
    for (long long i = blockIdx.x * 256ll + threadIdx.x; i < n;
         i += (long long)gridDim.x * 256) {
        __half h, l;
        split2h(in[i], h, l);
        oh[i] = h; ol[i] = l;
    }
}

// ---------------------------------------------------------------------------
// transpose + split fp16 hi/lo (z-batched)
// ---------------------------------------------------------------------------
__global__ void __launch_bounds__(256) tsplit_k(const float* __restrict__ in,
                                                __half* __restrict__ oh,
                                                __half* __restrict__ ol,
                                                int R, int C,
                                                long long inB, long long outB)
{
    __shared__ float t[32][33];
    const int b = blockIdx.z;
    in += b * inB; oh += b * outB; ol += b * outB;
    const int x = blockIdx.x * 32 + threadIdx.x;
    const int y0 = blockIdx.y * 32;
    #pragma unroll
    for (int i = 0; i < 4; ++i)
        t[threadIdx.y + i * 8][threadIdx.x] =
            in[(long long)(y0 + threadIdx.y + i * 8) * C + x];
    __syncthreads();
    const int ox = y0 + threadIdx.x;
    const int oy = blockIdx.x * 32;
    #pragma unroll
    for (int i = 0; i < 4; ++i) {
        const float v = t[threadIdx.x][threadIdx.y + i * 8];
        __half h, l;
        split2h(v, h, l);
        const long long o = (long long)(oy + threadIdx.y + i * 8) * R + ox;
        oh[o] = h; ol[o] = l;
    }
}

// transpose all 4 weight matrices, hi only (2-product B operand)
__global__ void __launch_bounds__(256) tsplit_w4(
    const float* __restrict__ in0, const float* __restrict__ in1,
    const float* __restrict__ in2, const float* __restrict__ in3,
    __half* __restrict__ oh)
{
    __shared__ float t[32][33];
    const int b = blockIdx.z;
    const float* in = (b == 0) ? in0 : (b == 1) ? in1 : (b == 2) ? in2 : in3;
    oh += (long long)b * ND * ND;
    const int x = blockIdx.x * 32 + threadIdx.x;
    const int y0 = blockIdx.y * 32;
    #pragma unroll
    for (int i = 0; i < 4; ++i)
        t[threadIdx.y + i * 8][threadIdx.x] =
            in[(long long)(y0 + threadIdx.y + i * 8) * ND + x];
    __syncthreads();
    const int oy = blockIdx.x * 32;
    const int ox = y0 + threadIdx.x;
    #pragma unroll
    for (int i = 0; i < 4; ++i) {
        const float v = t[threadIdx.x][threadIdx.y + i * 8];
        const long long o = (long long)(oy + threadIdx.y + i * 8) * ND + ox;
        oh[o] = __float2half(v);
    }
}

__global__ void __launch_bounds__(256) zero_l(float* __restrict__ l)
{
    const int i = blockIdx.x * 256 + threadIdx.x;
    ((float4*)l)[i] = make_float4(0.f, 0.f, 0.f, 0.f);
}

// ---------------------------------------------------------------------------
extern "C" void kernel_launch(void* const* d_in, const int* in_sizes, int n_in,
                              void* d_out, int out_size)
{
    (void)in_sizes; (void)n_in; (void)out_size;
    const float* x  = (const float*)d_in[0];
    const float* Wq = (const float*)d_in[2];
    const float* bq = (const float*)d_in[3];
    const float* Wk = (const float*)d_in[4];
    const float* bk = (const float*)d_in[5];
    const float* Wv = (const float*)d_in[6];
    const float* bv = (const float*)d_in[7];
    const float* Wo = (const float*)d_in[8];
    const float* bo = (const float*)d_in[9];
    float* out = (float*)d_out;

    __half *xh, *xl, *wth, *qh, *ql, *kh, *vth, *vtl, *ph, *oh, *ol;
    float *v32, *lb;
    cudaGetSymbolAddress((void**)&xh,  g_xh);
    cudaGetSymbolAddress((void**)&xl,  g_xl);
    cudaGetSymbolAddress((void**)&wth, g_wth);
    cudaGetSymbolAddress((void**)&qh,  g_qh);
    cudaGetSymbolAddress((void**)&ql,  g_ql);
    cudaGetSymbolAddress((void**)&kh,  g_kh);
    cudaGetSymbolAddress((void**)&v32, g_v);
    cudaGetSymbolAddress((void**)&vth, g_vth);
    cudaGetSymbolAddress((void**)&vtl, g_vtl);
    cudaGetSymbolAddress((void**)&ph,  g_ph);
    cudaGetSymbolAddress((void**)&lb,  g_l);
    cudaGetSymbolAddress((void**)&oh,  g_oh);
    cudaGetSymbolAddress((void**)&ol,  g_ol);

    cudaFuncSetAttribute((const void*)gemm_u<2, 1, 0>,
        cudaFuncAttributeMaxDynamicSharedMemorySize, 3 * 24576);
    cudaFuncSetAttribute((const void*)gemm_u<2, 1, 1>,
        cudaFuncAttributeMaxDynamicSharedMemorySize, 3 * 24576);
    cudaFuncSetAttribute((const void*)gemm_u<2, 1, 4>,
        cudaFuncAttributeMaxDynamicSharedMemorySize, 3 * 24576);
    cudaFuncSetAttribute((const void*)gemm_u<2, 1, 2>,
        cudaFuncAttributeMaxDynamicSharedMemorySize, 3 * 24576);
    cudaFuncSetAttribute((const void*)gemm_u<1, 2, 3>,
        cudaFuncAttributeMaxDynamicSharedMemorySize, 3 * 24576);

    const long long sSD = (long long)NS * ND;
    const long long sSS = (long long)NS * NS;
    const long long WSZ = (long long)ND * ND;

    // launch 0: split x
    split_k<<<32768, 256>>>(x, xh, xl, (long long)TOK * ND);
    // launch 1: transpose weights (hi only)
    {
        dim3 g(ND / 32, ND / 32, 4), b(32, 8, 1);
        tsplit_w4<<<g, b>>>(Wq, Wk, Wv, Wo, wth);
    }
    // launch 2: zero row-sum buffer
    zero_l<<<(NB * NH * NS) / 1024, 256>>>(lb);

    // launches 3-5: Q/K/V projections (exact-A x fp16-W, 2 products)
    const dim3 gproj(ND / 128, TOK / 128, 1);
    gemm_u<2, 1, 1><<<gproj, 256, 3 * 24576>>>(xh, xl, wth + 0 * WSZ, nullptr,
        bq, nullptr, 1.0f, nullptr, qh, ql,
        ND, ND, ND, ND, 1, 0, 0, 0, 0, 0, 0, 0);
    gemm_u<2, 1, 4><<<gproj, 256, 3 * 24576>>>(xh, xl, wth + 1 * WSZ, nullptr,
        bk, nullptr, 1.0f, nullptr, kh, nullptr,
        ND, ND, ND, ND, 1, 0, 0, 0, 0, 0, 0, 0);
    gemm_u<2, 1, 0><<<gproj, 256, 3 * 24576>>>(xh, xl, wth + 2 * WSZ, nullptr,
        bv, nullptr, 1.0f, v32, nullptr, nullptr,
        ND, ND, ND, ND, 1, 0, 0, 0, 0, 0, 0, 0);

    // launch 6: transpose+split V per batch: [S,D] -> [D,S]
    {
        dim3 g(ND / 32, NS / 32, NB), b(32, 8, 1);
        tsplit_k<<<g, b>>>(v32, vth, vtl, NS, ND, sSD, sSD);
    }

    // launch 7: QK -> P = exp(scale*QK^T) fp16 hi + row sums
    // 2 products: exact-Q x fp16-K
    {
        dim3 g(NS / 128, NS / 128, NB * NH);
        gemm_u<2, 1, 2><<<g, 256, 3 * 24576>>>(qh, ql, kh, nullptr,
            nullptr, lb, ATT_SCALE, nullptr, ph, nullptr,
            HD, ND, ND, NS, NH, sSD, HD, sSD, HD,
            (long long)NH * sSS, sSS, NS);
    }

    // launch 8: O = (P/l) V  (fp16-P x exact-V, 2 products, row-scaled)
    {
        dim3 g(1, NS / 128, NB * NH);
        gemm_u<1, 2, 3><<<g, 256, 3 * 24576>>>(ph, nullptr, vth, vtl,
            nullptr, lb, 1.0f, nullptr, oh, ol,
            NS, NS, NS, ND, NH, (long long)NH * sSS, sSS,
            sSD, (long long)HD * NS, sSD, HD, NS);
    }

    // launch 9: final projection -> d_out (exact-O x fp16-W, 2 products)
    gemm_u<2, 1, 0><<<gproj, 256, 3 * 24576>>>(oh, ol, wth + 3 * WSZ, nullptr,
        bo, nullptr, 1.0f, out, nullptr, nullptr,
        ND, ND, ND, ND, 1, 0, 0, 0, 0, 0, 0, 0);
}